// round 9
// baseline (speedup 1.0000x reference)
#include <cuda_runtime.h>
#include <cuda_fp16.h>
#include <cstdint>

// ---------------- problem constants ----------------
#define NTOK  197
#define BTOT  128          // B*T
#define OC3   2304         // 3*C
#define NCOLS 25216        // BTOT*NTOK
#define OUTBT 453888       // OC3*NTOK

// ---------------- device scratch (static globals: allowed) ----------------
__device__ float  g_s[BTOT * OC3];              // routing scales, 1.18 MB
__device__ __half g_wth[OC3 * 768];             // fp16(W), 3.5 MB
__device__ __half g_xsh[3][NCOLS * 768];        // fp16(x*s) per group, 116 MB

// ---------------- helpers ----------------
__device__ __forceinline__ uint32_t smem_u32(const void* p) {
    uint32_t a;
    asm("{ .reg .u64 t; cvta.to.shared.u64 t, %1; cvt.u32.u64 %0, t; }" : "=r"(a) : "l"(p));
    return a;
}
__device__ __forceinline__ void cp_async16(uint32_t dst, const void* src) {
    asm volatile("cp.async.cg.shared.global [%0], [%1], 16;" :: "r"(dst), "l"(src) : "memory");
}
#define CP_COMMIT() asm volatile("cp.async.commit_group;" ::: "memory")
#define CP_WAIT2()  asm volatile("cp.async.wait_group 2;" ::: "memory")
#define CP_WAIT1()  asm volatile("cp.async.wait_group 1;" ::: "memory")
#define CP_WAIT0()  asm volatile("cp.async.wait_group 0;" ::: "memory")

#define LDSM_X4(r0, r1, r2, r3, addr) \
    asm volatile("ldmatrix.sync.aligned.m8n8.x4.shared.b16 {%0,%1,%2,%3}, [%4];" \
        : "=r"(r0), "=r"(r1), "=r"(r2), "=r"(r3) : "r"(addr))

#define SWZ(off) ((off) ^ (((off) >> 3) & 0x70))

// ---------------------------------------------------------------------------
// Routing: r[b,oc,t] = conv1d_k3(cls)[oc,t] + ab[oc] + 1 -> g_s[(b*8+t)*2304+oc]
// ---------------------------------------------------------------------------
__global__ __launch_bounds__(256) void routing_kernel(
    const float* __restrict__ x, const float* __restrict__ aw,
    const float* __restrict__ ab)
{
    __shared__ float cls[10][772];   // rows 1..8 = cls(t), 0/9 zero pad
    const int b   = blockIdx.x;
    const int oc  = blockIdx.y * 256 + threadIdx.x;
    const int tid = threadIdx.x;

    #pragma unroll
    for (int tp = 0; tp < 8; tp++)
        for (int ic = tid; ic < 768; ic += 256)
            cls[tp + 1][ic] = x[(size_t)((b * 8 + tp) * 197) * 768 + ic];
    for (int ic = tid; ic < 772; ic += 256) { cls[0][ic] = 0.f; cls[9][ic] = 0.f; }
    __syncthreads();

    const float* wr = aw + (size_t)oc * 2304;   // aw[oc][ic][k]
    float acc[8];
    #pragma unroll
    for (int t = 0; t < 8; t++) acc[t] = 0.f;

    for (int ic = 0; ic < 768; ic += 4) {
        float4 w0 = *(const float4*)(wr + ic * 3);
        float4 w1 = *(const float4*)(wr + ic * 3 + 4);
        float4 w2 = *(const float4*)(wr + ic * 3 + 8);
        float cv[10][4];
        #pragma unroll
        for (int j = 0; j < 10; j++) {
            cv[j][0] = cls[j][ic];     cv[j][1] = cls[j][ic + 1];
            cv[j][2] = cls[j][ic + 2]; cv[j][3] = cls[j][ic + 3];
        }
        #pragma unroll
        for (int t = 0; t < 8; t++) {
            acc[t] += cv[t][0] * w0.x + cv[t+1][0] * w0.y + cv[t+2][0] * w0.z;
            acc[t] += cv[t][1] * w0.w + cv[t+1][1] * w1.x + cv[t+2][1] * w1.y;
            acc[t] += cv[t][2] * w1.z + cv[t+1][2] * w1.w + cv[t+2][2] * w2.x;
            acc[t] += cv[t][3] * w2.y + cv[t+1][3] * w2.z + cv[t+2][3] * w2.w;
        }
    }
    float abv = ab[oc] + 1.0f;
    #pragma unroll
    for (int t = 0; t < 8; t++)
        g_s[(b * 8 + t) * 2304 + oc] = acc[t] + abv;
}

// ---------------------------------------------------------------------------
// Prep: W -> fp16(RN) ;  x,s -> fp16(x*s) per group
// ---------------------------------------------------------------------------
__global__ __launch_bounds__(256) void prep_w(const float* __restrict__ w)
{
    int i = (blockIdx.x * 256 + threadIdx.x) * 4;
    float4 v = *(const float4*)(w + i);
    __half2 h0 = __floats2half2_rn(v.x, v.y);
    __half2 h1 = __floats2half2_rn(v.z, v.w);
    uint2 o = { *(uint32_t*)&h0, *(uint32_t*)&h1 };
    *(uint2*)(&g_wth[i]) = o;
}

__global__ __launch_bounds__(192) void prep_xs(const float* __restrict__ x)
{
    const int col = blockIdx.x;
    const int k   = threadIdx.x * 4;
    const int bt  = col / 197;
    float4 xv = *(const float4*)(x + (size_t)col * 768 + k);
    #pragma unroll
    for (int g = 0; g < 3; g++) {
        float4 sv = *(const float4*)(g_s + bt * 2304 + g * 768 + k);
        __half2 h0 = __floats2half2_rn(xv.x * sv.x, xv.y * sv.y);
        __half2 h1 = __floats2half2_rn(xv.z * sv.z, xv.w * sv.w);
        uint2 o = { *(uint32_t*)&h0, *(uint32_t*)&h1 };
        *(uint2*)(&g_xsh[g][(size_t)col * 768 + k]) = o;
    }
}

// ---------------------------------------------------------------------------
// Main GEMM (mma.sync fp16 m16n8k16): per g, out[o,cj] = sum_k Wh[o,k]*Xh[cj,k]
// CTA tile 256x128, BK=64 halfs, 12 chunks, 4-stage cp.async, tail-exact waits.
// 8 warps = 4(m) x 2(n): warp tile 64x64. 1 CTA/SM. grid=(9,197), block 256.
// ---------------------------------------------------------------------------
#define STAGES      4
#define A_BYTES     32768            // 256 rows x 128B
#define B_BYTES     16384            // 128 rows x 128B
#define STAGE_BYTES (A_BYTES + B_BYTES)
#define SMEM_MAIN   (STAGES * STAGE_BYTES)   // 196608
#define NCHUNK      12

__global__ __launch_bounds__(256, 1)
void tal_main_kernel(const float* __restrict__ bias, float* __restrict__ out)
{
    extern __shared__ char smem[];
    const uint32_t sb = smem_u32(smem);

    const int bx   = blockIdx.x;          // 0..8
    const int g    = bx / 3, mt = bx % 3;  // mt: 256-row M tile
    const int col0 = blockIdx.y * 128;
    const int tid  = threadIdx.x;
    const int lane = tid & 31, warp = tid >> 5;
    const int wm = warp & 3, wn = warp >> 2;      // 4x2 warp grid, 64x64 tiles
    const int lr = lane >> 2, lc = lane & 3;

    // ---- cp.async addressing: one base each; constant strides ----
    const int r0 = tid >> 3, q8 = (tid & 7) * 8;        // 8 halfs = 16B granule
    const uint32_t dst0 = SWZ((uint32_t)(r0 * 128 + q8 * 2));
    const __half* aptr = g_wth + (size_t)(g * 768 + mt * 256 + r0) * 768 + q8;
    const __half* bptr = g_xsh[g] + (size_t)(col0 + r0) * 768 + q8;

    // ---- ldmatrix base offsets (ks=0); per-ks addr = base ^ (ks*32) ----
    const int alrow = lane & 15, aqhi = lane >> 4;
    const int brow = (lane & 7) | ((lane & 16) >> 1), bq = (lane >> 3) & 1;
    uint32_t aoff[4], boff[4];
    #pragma unroll
    for (int mi = 0; mi < 4; mi++)
        aoff[mi] = SWZ((uint32_t)((wm * 64 + mi * 16 + alrow) * 128 + aqhi * 16));
    #pragma unroll
    for (int nj = 0; nj < 4; nj++)
        boff[nj] = SWZ((uint32_t)((wn * 64 + nj * 16 + brow) * 128 + bq * 16));

    float acc[4][8][4];
    #pragma unroll
    for (int mi = 0; mi < 4; mi++)
        #pragma unroll
        for (int ni = 0; ni < 8; ni++)
            #pragma unroll
            for (int e = 0; e < 4; e++) acc[mi][ni][e] = 0.f;

    auto COPY = [&](int st, int c) {
        const uint32_t sA = sb + st * STAGE_BYTES;
        const uint32_t sB = sA + A_BYTES;
        const __half* ap = aptr + c * 64;
        const __half* bp = bptr + c * 64;
        #pragma unroll
        for (int i = 0; i < 8; i++)            // A: 256 rows, 32 rows/pass
            cp_async16(sA + dst0 + i * 4096, ap + i * 24576);
        #pragma unroll
        for (int i = 0; i < 4; i++)            // B: 128 rows, 32 rows/pass
            cp_async16(sB + dst0 + i * 4096, bp + i * 24576);
    };

    COPY(0, 0); CP_COMMIT();
    COPY(1, 1); CP_COMMIT();
    COPY(2, 2); CP_COMMIT();

    #pragma unroll 1
    for (int c = 0; c < NCHUNK; c++) {
        if (c <= NCHUNK - 3)      { CP_WAIT2(); }
        else if (c == NCHUNK - 2) { CP_WAIT1(); }
        else                      { CP_WAIT0(); }
        __syncthreads();
        if (c + 3 < NCHUNK) { COPY((c + 3) & 3, c + 3); CP_COMMIT(); }

        const uint32_t sA = sb + (c & 3) * STAGE_BYTES;
        const uint32_t sB = sA + A_BYTES;

        #pragma unroll
        for (int ks = 0; ks < 4; ks++) {           // k16 steps within 64-half chunk
            const uint32_t kx = (uint32_t)(ks * 32);
            uint32_t a[4][4], b[4][4];
            #pragma unroll
            for (int mi = 0; mi < 4; mi++)
                LDSM_X4(a[mi][0], a[mi][1], a[mi][2], a[mi][3], sA + (aoff[mi] ^ kx));
            #pragma unroll
            for (int nj = 0; nj < 4; nj++)
                LDSM_X4(b[nj][0], b[nj][1], b[nj][2], b[nj][3], sB + (boff[nj] ^ kx));
            #pragma unroll
            for (int mi = 0; mi < 4; mi++)
                #pragma unroll
                for (int ni = 0; ni < 8; ni++) {
                    const uint32_t b0 = b[ni >> 1][(ni & 1) * 2];
                    const uint32_t b1 = b[ni >> 1][(ni & 1) * 2 + 1];
                    asm volatile(
                        "mma.sync.aligned.m16n8k16.row.col.f32.f16.f16.f32 "
                        "{%0,%1,%2,%3},{%4,%5,%6,%7},{%8,%9},{%0,%1,%2,%3};\n"
                        : "+f"(acc[mi][ni][0]), "+f"(acc[mi][ni][1]),
                          "+f"(acc[mi][ni][2]), "+f"(acc[mi][ni][3])
                        : "r"(a[mi][0]), "r"(a[mi][1]), "r"(a[mi][2]), "r"(a[mi][3]),
                          "r"(b0), "r"(b1));
                }
        }
    }

    // ---- epilogue: out[bt, oc, n] = acc + bias[oc]*s[bt,oc] ----
    const int bt_base = col0 / 197;
    const int col197  = (bt_base + 1) * 197;
    int bt1 = bt_base + 1; if (bt1 > 127) bt1 = 127;

    float bvsv[4][2][2];
    #pragma unroll
    for (int mi = 0; mi < 4; mi++)
        #pragma unroll
        for (int h = 0; h < 2; h++) {
            int oc = g * 768 + mt * 256 + wm * 64 + mi * 16 + lr + h * 8;
            float bv = bias[oc];
            bvsv[mi][h][0] = bv * g_s[bt_base * 2304 + oc];
            bvsv[mi][h][1] = bv * g_s[bt1 * 2304 + oc];
        }

    #pragma unroll
    for (int mi = 0; mi < 4; mi++)
        #pragma unroll
        for (int ni = 0; ni < 8; ni++)
            #pragma unroll
            for (int e = 0; e < 4; e++) {
                const int h   = e >> 1;
                const int oc  = g * 768 + mt * 256 + wm * 64 + mi * 16 + lr + h * 8;
                const int col = col0 + wn * 64 + ni * 8 + lc * 2 + (e & 1);
                const int bs  = (col >= col197) ? 1 : 0;
                const float add = bs ? bvsv[mi][h][1] : bvsv[mi][h][0];
                // idx = bt*OUTBT + oc*197 + (col - bt*197) = col + oc*197 + bt*453691
                const size_t idx = (size_t)col + (size_t)oc * 197
                                 + (size_t)(bt_base + bs) * 453691;
                out[idx] = acc[mi][ni][e] + add;
            }
}

extern "C" void kernel_launch(void* const* d_in, const int* in_sizes, int n_in,
                              void* d_out, int out_size)
{
    const float* x    = (const float*)d_in[0];
    const float* aw   = (const float*)d_in[1];
    const float* ab   = (const float*)d_in[2];
    const float* w    = (const float*)d_in[3];
    const float* bias = (const float*)d_in[4];
    float* out = (float*)d_out;

    cudaFuncSetAttribute(tal_main_kernel,
                         cudaFuncAttributeMaxDynamicSharedMemorySize, SMEM_MAIN);

    routing_kernel<<<dim3(16, 9), 256>>>(x, aw, ab);
    prep_w<<<OC3 * 768 / 1024, 256>>>(w);
    prep_xs<<<NCOLS, 192>>>(x);
    tal_main_kernel<<<dim3(9, 197), 256, SMEM_MAIN>>>(bias, out);
}

// round 10
// speedup vs baseline: 1.4948x; 1.4948x over previous
#include <cuda_runtime.h>
#include <cuda_fp16.h>
#include <cstdint>

// ---------------- problem constants ----------------
#define NTOK  197
#define BTOT  128          // B*T
#define OC3   2304         // 3*C
#define NCOLS 25216        // BTOT*NTOK
#define OUTBT 453888       // OC3*NTOK

// ---------------- device scratch (static globals: allowed) ----------------
__device__ float  g_s[BTOT * OC3];              // routing scales, 1.18 MB
__device__ __half g_wth[OC3 * 768];             // fp16(W), 3.5 MB
__device__ __half g_xsh[3][NCOLS * 768];        // fp16(x*s) per group, 116 MB

// ---------------- helpers ----------------
__device__ __forceinline__ uint32_t smem_u32(const void* p) {
    uint32_t a;
    asm("{ .reg .u64 t; cvta.to.shared.u64 t, %1; cvt.u32.u64 %0, t; }" : "=r"(a) : "l"(p));
    return a;
}
__device__ __forceinline__ void cp_async16(uint32_t dst, const void* src) {
    asm volatile("cp.async.cg.shared.global [%0], [%1], 16;" :: "r"(dst), "l"(src) : "memory");
}
#define CP_COMMIT() asm volatile("cp.async.commit_group;" ::: "memory")
#define CP_WAIT2()  asm volatile("cp.async.wait_group 2;" ::: "memory")
#define CP_WAIT1()  asm volatile("cp.async.wait_group 1;" ::: "memory")
#define CP_WAIT0()  asm volatile("cp.async.wait_group 0;" ::: "memory")

#define LDSM_X4(r0, r1, r2, r3, addr) \
    asm volatile("ldmatrix.sync.aligned.m8n8.x4.shared.b16 {%0,%1,%2,%3}, [%4];" \
        : "=r"(r0), "=r"(r1), "=r"(r2), "=r"(r3) : "r"(addr))

#define SWZ(off) ((off) ^ (((off) >> 3) & 0x70))

// ---------------------------------------------------------------------------
// Routing: r[b,oc,t] = conv1d_k3(cls)[oc,t] + ab[oc] + 1 -> g_s[(b*8+t)*2304+oc]
// ---------------------------------------------------------------------------
__global__ __launch_bounds__(256) void routing_kernel(
    const float* __restrict__ x, const float* __restrict__ aw,
    const float* __restrict__ ab)
{
    __shared__ float cls[10][772];   // rows 1..8 = cls(t), 0/9 zero pad
    const int b   = blockIdx.x;
    const int oc  = blockIdx.y * 256 + threadIdx.x;
    const int tid = threadIdx.x;

    #pragma unroll
    for (int tp = 0; tp < 8; tp++)
        for (int ic = tid; ic < 768; ic += 256)
            cls[tp + 1][ic] = x[(size_t)((b * 8 + tp) * 197) * 768 + ic];
    for (int ic = tid; ic < 772; ic += 256) { cls[0][ic] = 0.f; cls[9][ic] = 0.f; }
    __syncthreads();

    const float* wr = aw + (size_t)oc * 2304;   // aw[oc][ic][k]
    float acc[8];
    #pragma unroll
    for (int t = 0; t < 8; t++) acc[t] = 0.f;

    for (int ic = 0; ic < 768; ic += 4) {
        float4 w0 = *(const float4*)(wr + ic * 3);
        float4 w1 = *(const float4*)(wr + ic * 3 + 4);
        float4 w2 = *(const float4*)(wr + ic * 3 + 8);
        float cv[10][4];
        #pragma unroll
        for (int j = 0; j < 10; j++) {
            cv[j][0] = cls[j][ic];     cv[j][1] = cls[j][ic + 1];
            cv[j][2] = cls[j][ic + 2]; cv[j][3] = cls[j][ic + 3];
        }
        #pragma unroll
        for (int t = 0; t < 8; t++) {
            acc[t] += cv[t][0] * w0.x + cv[t+1][0] * w0.y + cv[t+2][0] * w0.z;
            acc[t] += cv[t][1] * w0.w + cv[t+1][1] * w1.x + cv[t+2][1] * w1.y;
            acc[t] += cv[t][2] * w1.z + cv[t+1][2] * w1.w + cv[t+2][2] * w2.x;
            acc[t] += cv[t][3] * w2.y + cv[t+1][3] * w2.z + cv[t+2][3] * w2.w;
        }
    }
    float abv = ab[oc] + 1.0f;
    #pragma unroll
    for (int t = 0; t < 8; t++)
        g_s[(b * 8 + t) * 2304 + oc] = acc[t] + abv;
}

// ---------------------------------------------------------------------------
// Prep: W -> fp16(RN) ;  x,s -> fp16(x*s) per group
// ---------------------------------------------------------------------------
__global__ __launch_bounds__(256) void prep_w(const float* __restrict__ w)
{
    int i = (blockIdx.x * 256 + threadIdx.x) * 4;
    float4 v = *(const float4*)(w + i);
    __half2 h0 = __floats2half2_rn(v.x, v.y);
    __half2 h1 = __floats2half2_rn(v.z, v.w);
    uint2 o = { *(uint32_t*)&h0, *(uint32_t*)&h1 };
    *(uint2*)(&g_wth[i]) = o;
}

__global__ __launch_bounds__(192) void prep_xs(const float* __restrict__ x)
{
    const int col = blockIdx.x;
    const int k   = threadIdx.x * 4;
    const int bt  = col / 197;
    float4 xv = *(const float4*)(x + (size_t)col * 768 + k);
    #pragma unroll
    for (int g = 0; g < 3; g++) {
        float4 sv = *(const float4*)(g_s + bt * 2304 + g * 768 + k);
        __half2 h0 = __floats2half2_rn(xv.x * sv.x, xv.y * sv.y);
        __half2 h1 = __floats2half2_rn(xv.z * sv.z, xv.w * sv.w);
        uint2 o = { *(uint32_t*)&h0, *(uint32_t*)&h1 };
        *(uint2*)(&g_xsh[g][(size_t)col * 768 + k]) = o;
    }
}

// ---------------------------------------------------------------------------
// Main GEMM (mma.sync fp16 m16n8k16): per g, out[o,cj] = sum_k Wh[o,k]*Xh[cj,k]
// CTA tile 256x128, BK=64 halfs, 12 chunks, 4-stage cp.async, tail-exact waits.
// 8 warps = 4(m) x 2(n): warp tile 64x64. 1 CTA/SM. grid=(9,197), block 256.
// ---------------------------------------------------------------------------
#define STAGES      4
#define A_BYTES     32768            // 256 rows x 128B
#define B_BYTES     16384            // 128 rows x 128B
#define STAGE_BYTES (A_BYTES + B_BYTES)
#define SMEM_MAIN   (STAGES * STAGE_BYTES)   // 196608
#define NCHUNK      12

__global__ __launch_bounds__(256, 1)
void tal_main_kernel(const float* __restrict__ bias, float* __restrict__ out)
{
    extern __shared__ char smem[];
    const uint32_t sb = smem_u32(smem);

    const int bx   = blockIdx.x;          // 0..8
    const int g    = bx / 3, mt = bx % 3;  // mt: 256-row M tile
    const int col0 = blockIdx.y * 128;
    const int tid  = threadIdx.x;
    const int lane = tid & 31, warp = tid >> 5;
    const int wm = warp & 3, wn = warp >> 2;      // 4x2 warp grid, 64x64 tiles
    const int lr = lane >> 2, lc = lane & 3;

    // ---- cp.async addressing: one base each; constant strides ----
    const int r0 = tid >> 3, q8 = (tid & 7) * 8;        // 8 halfs = 16B granule
    const uint32_t dst0 = SWZ((uint32_t)(r0 * 128 + q8 * 2));
    const __half* aptr = g_wth + (size_t)(g * 768 + mt * 256 + r0) * 768 + q8;
    const __half* bptr = g_xsh[g] + (size_t)(col0 + r0) * 768 + q8;

    // ---- ldmatrix base offsets (ks=0); per-ks addr = base ^ (ks*32) ----
    const int alrow = lane & 15, aqhi = lane >> 4;
    const int brow = (lane & 7) | ((lane & 16) >> 1), bq = (lane >> 3) & 1;
    uint32_t aoff[4], boff[4];
    #pragma unroll
    for (int mi = 0; mi < 4; mi++)
        aoff[mi] = SWZ((uint32_t)((wm * 64 + mi * 16 + alrow) * 128 + aqhi * 16));
    #pragma unroll
    for (int nj = 0; nj < 4; nj++)
        boff[nj] = SWZ((uint32_t)((wn * 64 + nj * 16 + brow) * 128 + bq * 16));

    float acc[4][8][4];
    #pragma unroll
    for (int mi = 0; mi < 4; mi++)
        #pragma unroll
        for (int ni = 0; ni < 8; ni++)
            #pragma unroll
            for (int e = 0; e < 4; e++) acc[mi][ni][e] = 0.f;

    auto COPY = [&](int st, int c) {
        const uint32_t sA = sb + st * STAGE_BYTES;
        const uint32_t sB = sA + A_BYTES;
        const __half* ap = aptr + c * 64;
        const __half* bp = bptr + c * 64;
        #pragma unroll
        for (int i = 0; i < 8; i++)            // A: 256 rows, 32 rows/pass
            cp_async16(sA + dst0 + i * 4096, ap + i * 24576);
        #pragma unroll
        for (int i = 0; i < 4; i++)            // B: 128 rows, 32 rows/pass
            cp_async16(sB + dst0 + i * 4096, bp + i * 24576);
    };

    COPY(0, 0); CP_COMMIT();
    COPY(1, 1); CP_COMMIT();
    COPY(2, 2); CP_COMMIT();

    #pragma unroll 1
    for (int c = 0; c < NCHUNK; c++) {
        if (c <= NCHUNK - 3)      { CP_WAIT2(); }
        else if (c == NCHUNK - 2) { CP_WAIT1(); }
        else                      { CP_WAIT0(); }
        __syncthreads();
        if (c + 3 < NCHUNK) { COPY((c + 3) & 3, c + 3); CP_COMMIT(); }

        const uint32_t sA = sb + (c & 3) * STAGE_BYTES;
        const uint32_t sB = sA + A_BYTES;

        #pragma unroll
        for (int ks = 0; ks < 4; ks++) {           // k16 steps within 64-half chunk
            const uint32_t kx = (uint32_t)(ks * 32);
            uint32_t a[4][4], b[4][4];
            #pragma unroll
            for (int mi = 0; mi < 4; mi++)
                LDSM_X4(a[mi][0], a[mi][1], a[mi][2], a[mi][3], sA + (aoff[mi] ^ kx));
            #pragma unroll
            for (int nj = 0; nj < 4; nj++)
                LDSM_X4(b[nj][0], b[nj][1], b[nj][2], b[nj][3], sB + (boff[nj] ^ kx));
            #pragma unroll
            for (int mi = 0; mi < 4; mi++)
                #pragma unroll
                for (int ni = 0; ni < 8; ni++) {
                    const uint32_t b0 = b[ni >> 1][(ni & 1) * 2];
                    const uint32_t b1 = b[ni >> 1][(ni & 1) * 2 + 1];
                    asm volatile(
                        "mma.sync.aligned.m16n8k16.row.col.f32.f16.f16.f32 "
                        "{%0,%1,%2,%3},{%4,%5,%6,%7},{%8,%9},{%0,%1,%2,%3};\n"
                        : "+f"(acc[mi][ni][0]), "+f"(acc[mi][ni][1]),
                          "+f"(acc[mi][ni][2]), "+f"(acc[mi][ni][3])
                        : "r"(a[mi][0]), "r"(a[mi][1]), "r"(a[mi][2]), "r"(a[mi][3]),
                          "r"(b0), "r"(b1));
                }
        }
    }

    // ---- epilogue: out[bt, oc, n] = acc + bias[oc]*s[bt,oc] ----
    const int bt_base = col0 / 197;
    const int col197  = (bt_base + 1) * 197;
    int bt1 = bt_base + 1; if (bt1 > 127) bt1 = 127;

    float bvsv[4][2][2];
    #pragma unroll
    for (int mi = 0; mi < 4; mi++)
        #pragma unroll
        for (int h = 0; h < 2; h++) {
            int oc = g * 768 + mt * 256 + wm * 64 + mi * 16 + lr + h * 8;
            float bv = bias[oc];
            bvsv[mi][h][0] = bv * g_s[bt_base * 2304 + oc];
            bvsv[mi][h][1] = bv * g_s[bt1 * 2304 + oc];
        }

    #pragma unroll
    for (int mi = 0; mi < 4; mi++)
        #pragma unroll
        for (int ni = 0; ni < 8; ni++)
            #pragma unroll
            for (int e = 0; e < 4; e++) {
                const int h   = e >> 1;
                const int oc  = g * 768 + mt * 256 + wm * 64 + mi * 16 + lr + h * 8;
                const int col = col0 + wn * 64 + ni * 8 + lc * 2 + (e & 1);
                const int bs  = (col >= col197) ? 1 : 0;
                const float add = bs ? bvsv[mi][h][1] : bvsv[mi][h][0];
                // idx = bt*OUTBT + oc*197 + (col - bt*197) = col + oc*197 + bt*453691
                const size_t idx = (size_t)col + (size_t)oc * 197
                                 + (size_t)(bt_base + bs) * 453691;
                out[idx] = acc[mi][ni][e] + add;
            }
}

extern "C" void kernel_launch(void* const* d_in, const int* in_sizes, int n_in,
                              void* d_out, int out_size)
{
    const float* x    = (const float*)d_in[0];
    const float* aw   = (const float*)d_in[1];
    const float* ab   = (const float*)d_in[2];
    const float* w    = (const float*)d_in[3];
    const float* bias = (const float*)d_in[4];
    float* out = (float*)d_out;

    cudaFuncSetAttribute(tal_main_kernel,
                         cudaFuncAttributeMaxDynamicSharedMemorySize, SMEM_MAIN);

    routing_kernel<<<dim3(16, 9), 256>>>(x, aw, ab);
    prep_w<<<OC3 * 768 / 1024, 256>>>(w);
    prep_xs<<<NCOLS, 192>>>(x);
    tal_main_kernel<<<dim3(9, 197), 256, SMEM_MAIN>>>(bias, out);
}

// round 11
// speedup vs baseline: 1.4979x; 1.0021x over previous
#include <cuda_runtime.h>
#include <cuda_fp16.h>
#include <cstdint>

// ---------------- problem constants ----------------
#define NTOK  197
#define BTOT  128          // B*T
#define OC3   2304         // 3*C
#define NCOLS 25216        // BTOT*NTOK
#define OUTBT 453888       // OC3*NTOK

// ---------------- device scratch (static globals: allowed) ----------------
__device__ float  g_s[BTOT * OC3];              // routing scales, 1.18 MB
__device__ __half g_wth[OC3 * 768];             // fp16(W), 3.5 MB
__device__ __half g_xsh[3][NCOLS * 768];        // fp16(x*s) per group, 116 MB

// ---------------- helpers ----------------
__device__ __forceinline__ uint32_t smem_u32(const void* p) {
    uint32_t a;
    asm("{ .reg .u64 t; cvta.to.shared.u64 t, %1; cvt.u32.u64 %0, t; }" : "=r"(a) : "l"(p));
    return a;
}
__device__ __forceinline__ void cp_async16(uint32_t dst, const void* src) {
    asm volatile("cp.async.cg.shared.global [%0], [%1], 16;" :: "r"(dst), "l"(src) : "memory");
}
#define CP_COMMIT() asm volatile("cp.async.commit_group;" ::: "memory")
#define CP_WAIT2()  asm volatile("cp.async.wait_group 2;" ::: "memory")
#define CP_WAIT1()  asm volatile("cp.async.wait_group 1;" ::: "memory")
#define CP_WAIT0()  asm volatile("cp.async.wait_group 0;" ::: "memory")

#define LDSM_X4(r0, r1, r2, r3, addr) \
    asm volatile("ldmatrix.sync.aligned.m8n8.x4.shared.b16 {%0,%1,%2,%3}, [%4];" \
        : "=r"(r0), "=r"(r1), "=r"(r2), "=r"(r3) : "r"(addr))

#define SWZ(off) ((off) ^ (((off) >> 3) & 0x70))

// ---------------------------------------------------------------------------
// Routing: r[b,oc,t] = conv1d_k3(cls)[oc,t] + ab[oc] + 1 -> g_s[(b*8+t)*2304+oc]
// ---------------------------------------------------------------------------
__global__ __launch_bounds__(256) void routing_kernel(
    const float* __restrict__ x, const float* __restrict__ aw,
    const float* __restrict__ ab)
{
    __shared__ float cls[10][772];   // rows 1..8 = cls(t), 0/9 zero pad
    const int b   = blockIdx.x;
    const int oc  = blockIdx.y * 256 + threadIdx.x;
    const int tid = threadIdx.x;

    #pragma unroll
    for (int tp = 0; tp < 8; tp++)
        for (int ic = tid; ic < 768; ic += 256)
            cls[tp + 1][ic] = x[(size_t)((b * 8 + tp) * 197) * 768 + ic];
    for (int ic = tid; ic < 772; ic += 256) { cls[0][ic] = 0.f; cls[9][ic] = 0.f; }
    __syncthreads();

    const float* wr = aw + (size_t)oc * 2304;   // aw[oc][ic][k]
    float acc[8];
    #pragma unroll
    for (int t = 0; t < 8; t++) acc[t] = 0.f;

    for (int ic = 0; ic < 768; ic += 4) {
        float4 w0 = *(const float4*)(wr + ic * 3);
        float4 w1 = *(const float4*)(wr + ic * 3 + 4);
        float4 w2 = *(const float4*)(wr + ic * 3 + 8);
        float cv[10][4];
        #pragma unroll
        for (int j = 0; j < 10; j++) {
            cv[j][0] = cls[j][ic];     cv[j][1] = cls[j][ic + 1];
            cv[j][2] = cls[j][ic + 2]; cv[j][3] = cls[j][ic + 3];
        }
        #pragma unroll
        for (int t = 0; t < 8; t++) {
            acc[t] += cv[t][0] * w0.x + cv[t+1][0] * w0.y + cv[t+2][0] * w0.z;
            acc[t] += cv[t][1] * w0.w + cv[t+1][1] * w1.x + cv[t+2][1] * w1.y;
            acc[t] += cv[t][2] * w1.z + cv[t+1][2] * w1.w + cv[t+2][2] * w2.x;
            acc[t] += cv[t][3] * w2.y + cv[t+1][3] * w2.z + cv[t+2][3] * w2.w;
        }
    }
    float abv = ab[oc] + 1.0f;
    #pragma unroll
    for (int t = 0; t < 8; t++)
        g_s[(b * 8 + t) * 2304 + oc] = acc[t] + abv;
}

// ---------------------------------------------------------------------------
// Prep: W -> fp16(RN) ;  x,s -> fp16(x*s) per group
// ---------------------------------------------------------------------------
__global__ __launch_bounds__(256) void prep_w(const float* __restrict__ w)
{
    int i = (blockIdx.x * 256 + threadIdx.x) * 4;
    float4 v = *(const float4*)(w + i);
    __half2 h0 = __floats2half2_rn(v.x, v.y);
    __half2 h1 = __floats2half2_rn(v.z, v.w);
    uint2 o = { *(uint32_t*)&h0, *(uint32_t*)&h1 };
    *(uint2*)(&g_wth[i]) = o;
}

__global__ __launch_bounds__(192) void prep_xs(const float* __restrict__ x)
{
    const int col = blockIdx.x;
    const int k   = threadIdx.x * 4;
    const int bt  = col / 197;
    float4 xv = *(const float4*)(x + (size_t)col * 768 + k);
    #pragma unroll
    for (int g = 0; g < 3; g++) {
        float4 sv = *(const float4*)(g_s + bt * 2304 + g * 768 + k);
        __half2 h0 = __floats2half2_rn(xv.x * sv.x, xv.y * sv.y);
        __half2 h1 = __floats2half2_rn(xv.z * sv.z, xv.w * sv.w);
        uint2 o = { *(uint32_t*)&h0, *(uint32_t*)&h1 };
        *(uint2*)(&g_xsh[g][(size_t)col * 768 + k]) = o;
    }
}

// ---------------------------------------------------------------------------
// Main GEMM (mma.sync fp16 m16n8k16): per g, out[o,cj] = sum_k Wh[o,k]*Xh[cj,k]
// CTA tile 256x128, BK=64 halfs, 12 chunks, 4-stage cp.async, tail-exact waits.
// 8 warps = 4(m) x 2(n): warp tile 64x64. 1 CTA/SM. grid=(9,197), block 256.
// ---------------------------------------------------------------------------
#define STAGES      4
#define A_BYTES     32768            // 256 rows x 128B
#define B_BYTES     16384            // 128 rows x 128B
#define STAGE_BYTES (A_BYTES + B_BYTES)
#define SMEM_MAIN   (STAGES * STAGE_BYTES)   // 196608
#define NCHUNK      12

__global__ __launch_bounds__(256, 1)
void tal_main_kernel(const float* __restrict__ bias, float* __restrict__ out)
{
    extern __shared__ char smem[];
    const uint32_t sb = smem_u32(smem);

    const int bx   = blockIdx.x;          // 0..8
    const int g    = bx / 3, mt = bx % 3;  // mt: 256-row M tile
    const int col0 = blockIdx.y * 128;
    const int tid  = threadIdx.x;
    const int lane = tid & 31, warp = tid >> 5;
    const int wm = warp & 3, wn = warp >> 2;      // 4x2 warp grid, 64x64 tiles
    const int lr = lane >> 2, lc = lane & 3;

    // ---- cp.async addressing: one base each; constant strides ----
    const int r0 = tid >> 3, q8 = (tid & 7) * 8;        // 8 halfs = 16B granule
    const uint32_t dst0 = SWZ((uint32_t)(r0 * 128 + q8 * 2));
    const __half* aptr = g_wth + (size_t)(g * 768 + mt * 256 + r0) * 768 + q8;
    const __half* bptr = g_xsh[g] + (size_t)(col0 + r0) * 768 + q8;

    // ---- ldmatrix base offsets (ks=0); per-ks addr = base ^ (ks*32) ----
    const int alrow = lane & 15, aqhi = lane >> 4;
    const int brow = (lane & 7) | ((lane & 16) >> 1), bq = (lane >> 3) & 1;
    uint32_t aoff[4], boff[4];
    #pragma unroll
    for (int mi = 0; mi < 4; mi++)
        aoff[mi] = SWZ((uint32_t)((wm * 64 + mi * 16 + alrow) * 128 + aqhi * 16));
    #pragma unroll
    for (int nj = 0; nj < 4; nj++)
        boff[nj] = SWZ((uint32_t)((wn * 64 + nj * 16 + brow) * 128 + bq * 16));

    float acc[4][8][4];
    #pragma unroll
    for (int mi = 0; mi < 4; mi++)
        #pragma unroll
        for (int ni = 0; ni < 8; ni++)
            #pragma unroll
            for (int e = 0; e < 4; e++) acc[mi][ni][e] = 0.f;

    auto COPY = [&](int st, int c) {
        const uint32_t sA = sb + st * STAGE_BYTES;
        const uint32_t sB = sA + A_BYTES;
        const __half* ap = aptr + c * 64;
        const __half* bp = bptr + c * 64;
        #pragma unroll
        for (int i = 0; i < 8; i++)            // A: 256 rows, 32 rows/pass
            cp_async16(sA + dst0 + i * 4096, ap + i * 24576);
        #pragma unroll
        for (int i = 0; i < 4; i++)            // B: 128 rows, 32 rows/pass
            cp_async16(sB + dst0 + i * 4096, bp + i * 24576);
    };

    COPY(0, 0); CP_COMMIT();
    COPY(1, 1); CP_COMMIT();
    COPY(2, 2); CP_COMMIT();

    #pragma unroll 1
    for (int c = 0; c < NCHUNK; c++) {
        if (c <= NCHUNK - 3)      { CP_WAIT2(); }
        else if (c == NCHUNK - 2) { CP_WAIT1(); }
        else                      { CP_WAIT0(); }
        __syncthreads();
        if (c + 3 < NCHUNK) { COPY((c + 3) & 3, c + 3); CP_COMMIT(); }

        const uint32_t sA = sb + (c & 3) * STAGE_BYTES;
        const uint32_t sB = sA + A_BYTES;

        #pragma unroll
        for (int ks = 0; ks < 4; ks++) {           // k16 steps within 64-half chunk
            const uint32_t kx = (uint32_t)(ks * 32);
            uint32_t a[4][4], b[4][4];
            #pragma unroll
            for (int mi = 0; mi < 4; mi++)
                LDSM_X4(a[mi][0], a[mi][1], a[mi][2], a[mi][3], sA + (aoff[mi] ^ kx));
            #pragma unroll
            for (int nj = 0; nj < 4; nj++)
                LDSM_X4(b[nj][0], b[nj][1], b[nj][2], b[nj][3], sB + (boff[nj] ^ kx));
            #pragma unroll
            for (int mi = 0; mi < 4; mi++)
                #pragma unroll
                for (int ni = 0; ni < 8; ni++) {
                    const uint32_t b0 = b[ni >> 1][(ni & 1) * 2];
                    const uint32_t b1 = b[ni >> 1][(ni & 1) * 2 + 1];
                    asm volatile(
                        "mma.sync.aligned.m16n8k16.row.col.f32.f16.f16.f32 "
                        "{%0,%1,%2,%3},{%4,%5,%6,%7},{%8,%9},{%0,%1,%2,%3};\n"
                        : "+f"(acc[mi][ni][0]), "+f"(acc[mi][ni][1]),
                          "+f"(acc[mi][ni][2]), "+f"(acc[mi][ni][3])
                        : "r"(a[mi][0]), "r"(a[mi][1]), "r"(a[mi][2]), "r"(a[mi][3]),
                          "r"(b0), "r"(b1));
                }
        }
    }

    // ---- epilogue: out[bt, oc, n] = acc + bias[oc]*s[bt,oc] ----
    const int bt_base = col0 / 197;
    const int col197  = (bt_base + 1) * 197;
    int bt1 = bt_base + 1; if (bt1 > 127) bt1 = 127;

    float bvsv[4][2][2];
    #pragma unroll
    for (int mi = 0; mi < 4; mi++)
        #pragma unroll
        for (int h = 0; h < 2; h++) {
            int oc = g * 768 + mt * 256 + wm * 64 + mi * 16 + lr + h * 8;
            float bv = bias[oc];
            bvsv[mi][h][0] = bv * g_s[bt_base * 2304 + oc];
            bvsv[mi][h][1] = bv * g_s[bt1 * 2304 + oc];
        }

    #pragma unroll
    for (int mi = 0; mi < 4; mi++)
        #pragma unroll
        for (int ni = 0; ni < 8; ni++)
            #pragma unroll
            for (int e = 0; e < 4; e++) {
                const int h   = e >> 1;
                const int oc  = g * 768 + mt * 256 + wm * 64 + mi * 16 + lr + h * 8;
                const int col = col0 + wn * 64 + ni * 8 + lc * 2 + (e & 1);
                const int bs  = (col >= col197) ? 1 : 0;
                const float add = bs ? bvsv[mi][h][1] : bvsv[mi][h][0];
                // idx = bt*OUTBT + oc*197 + (col - bt*197) = col + oc*197 + bt*453691
                const size_t idx = (size_t)col + (size_t)oc * 197
                                 + (size_t)(bt_base + bs) * 453691;
                out[idx] = acc[mi][ni][e] + add;
            }
}

extern "C" void kernel_launch(void* const* d_in, const int* in_sizes, int n_in,
                              void* d_out, int out_size)
{
    const float* x    = (const float*)d_in[0];
    const float* aw   = (const float*)d_in[1];
    const float* ab   = (const float*)d_in[2];
    const float* w    = (const float*)d_in[3];
    const float* bias = (const float*)d_in[4];
    float* out = (float*)d_out;

    cudaFuncSetAttribute(tal_main_kernel,
                         cudaFuncAttributeMaxDynamicSharedMemorySize, SMEM_MAIN);

    routing_kernel<<<dim3(16, 9), 256>>>(x, aw, ab);
    prep_w<<<OC3 * 768 / 1024, 256>>>(w);
    prep_xs<<<NCOLS, 192>>>(x);
    tal_main_kernel<<<dim3(9, 197), 256, SMEM_MAIN>>>(bias, out);
}

// round 12
// speedup vs baseline: 1.4982x; 1.0002x over previous
#include <cuda_runtime.h>
#include <cuda_fp16.h>
#include <cstdint>

// ---------------- problem constants ----------------
#define NTOK  197
#define BTOT  128          // B*T
#define OC3   2304         // 3*C
#define NCOLS 25216        // BTOT*NTOK
#define OUTBT 453888       // OC3*NTOK

// ---------------- device scratch (static globals: allowed) ----------------
__device__ float  g_s[BTOT * OC3];              // routing scales, 1.18 MB
__device__ __half g_wth[OC3 * 768];             // fp16(W), 3.5 MB
__device__ __half g_xsh[3][NCOLS * 768];        // fp16(x*s) per group, 116 MB

// ---------------- helpers ----------------
__device__ __forceinline__ uint32_t smem_u32(const void* p) {
    uint32_t a;
    asm("{ .reg .u64 t; cvta.to.shared.u64 t, %1; cvt.u32.u64 %0, t; }" : "=r"(a) : "l"(p));
    return a;
}
__device__ __forceinline__ void cp_async16(uint32_t dst, const void* src) {
    asm volatile("cp.async.cg.shared.global [%0], [%1], 16;" :: "r"(dst), "l"(src) : "memory");
}
#define CP_COMMIT() asm volatile("cp.async.commit_group;" ::: "memory")
#define CP_WAIT2()  asm volatile("cp.async.wait_group 2;" ::: "memory")
#define CP_WAIT1()  asm volatile("cp.async.wait_group 1;" ::: "memory")
#define CP_WAIT0()  asm volatile("cp.async.wait_group 0;" ::: "memory")

#define LDSM_X4(r0, r1, r2, r3, addr) \
    asm volatile("ldmatrix.sync.aligned.m8n8.x4.shared.b16 {%0,%1,%2,%3}, [%4];" \
        : "=r"(r0), "=r"(r1), "=r"(r2), "=r"(r3) : "r"(addr))

#define SWZ(off) ((off) ^ (((off) >> 3) & 0x70))

// ---------------------------------------------------------------------------
// Routing: r[b,oc,t] = conv1d_k3(cls)[oc,t] + ab[oc] + 1 -> g_s[(b*8+t)*2304+oc]
// ---------------------------------------------------------------------------
__global__ __launch_bounds__(256) void routing_kernel(
    const float* __restrict__ x, const float* __restrict__ aw,
    const float* __restrict__ ab)
{
    __shared__ float cls[10][772];   // rows 1..8 = cls(t), 0/9 zero pad
    const int b   = blockIdx.x;
    const int oc  = blockIdx.y * 256 + threadIdx.x;
    const int tid = threadIdx.x;

    #pragma unroll
    for (int tp = 0; tp < 8; tp++)
        for (int ic = tid; ic < 768; ic += 256)
            cls[tp + 1][ic] = x[(size_t)((b * 8 + tp) * 197) * 768 + ic];
    for (int ic = tid; ic < 772; ic += 256) { cls[0][ic] = 0.f; cls[9][ic] = 0.f; }
    __syncthreads();

    const float* wr = aw + (size_t)oc * 2304;   // aw[oc][ic][k]
    float acc[8];
    #pragma unroll
    for (int t = 0; t < 8; t++) acc[t] = 0.f;

    for (int ic = 0; ic < 768; ic += 4) {
        float4 w0 = *(const float4*)(wr + ic * 3);
        float4 w1 = *(const float4*)(wr + ic * 3 + 4);
        float4 w2 = *(const float4*)(wr + ic * 3 + 8);
        float cv[10][4];
        #pragma unroll
        for (int j = 0; j < 10; j++) {
            cv[j][0] = cls[j][ic];     cv[j][1] = cls[j][ic + 1];
            cv[j][2] = cls[j][ic + 2]; cv[j][3] = cls[j][ic + 3];
        }
        #pragma unroll
        for (int t = 0; t < 8; t++) {
            acc[t] += cv[t][0] * w0.x + cv[t+1][0] * w0.y + cv[t+2][0] * w0.z;
            acc[t] += cv[t][1] * w0.w + cv[t+1][1] * w1.x + cv[t+2][1] * w1.y;
            acc[t] += cv[t][2] * w1.z + cv[t+1][2] * w1.w + cv[t+2][2] * w2.x;
            acc[t] += cv[t][3] * w2.y + cv[t+1][3] * w2.z + cv[t+2][3] * w2.w;
        }
    }
    float abv = ab[oc] + 1.0f;
    #pragma unroll
    for (int t = 0; t < 8; t++)
        g_s[(b * 8 + t) * 2304 + oc] = acc[t] + abv;
}

// ---------------------------------------------------------------------------
// Prep: W -> fp16(RN) ;  x,s -> fp16(x*s) per group
// ---------------------------------------------------------------------------
__global__ __launch_bounds__(256) void prep_w(const float* __restrict__ w)
{
    int i = (blockIdx.x * 256 + threadIdx.x) * 4;
    float4 v = *(const float4*)(w + i);
    __half2 h0 = __floats2half2_rn(v.x, v.y);
    __half2 h1 = __floats2half2_rn(v.z, v.w);
    uint2 o = { *(uint32_t*)&h0, *(uint32_t*)&h1 };
    *(uint2*)(&g_wth[i]) = o;
}

__global__ __launch_bounds__(192) void prep_xs(const float* __restrict__ x)
{
    const int col = blockIdx.x;
    const int k   = threadIdx.x * 4;
    const int bt  = col / 197;
    float4 xv = *(const float4*)(x + (size_t)col * 768 + k);
    #pragma unroll
    for (int g = 0; g < 3; g++) {
        float4 sv = *(const float4*)(g_s + bt * 2304 + g * 768 + k);
        __half2 h0 = __floats2half2_rn(xv.x * sv.x, xv.y * sv.y);
        __half2 h1 = __floats2half2_rn(xv.z * sv.z, xv.w * sv.w);
        uint2 o = { *(uint32_t*)&h0, *(uint32_t*)&h1 };
        *(uint2*)(&g_xsh[g][(size_t)col * 768 + k]) = o;
    }
}

// ---------------------------------------------------------------------------
// Main GEMM (mma.sync fp16 m16n8k16): per g, out[o,cj] = sum_k Wh[o,k]*Xh[cj,k]
// CTA tile 256x128, BK=64 halfs, 12 chunks, 4-stage cp.async, tail-exact waits.
// 8 warps = 4(m) x 2(n): warp tile 64x64. 1 CTA/SM. grid=(9,197), block 256.
// ---------------------------------------------------------------------------
#define STAGES      4
#define A_BYTES     32768            // 256 rows x 128B
#define B_BYTES     16384            // 128 rows x 128B
#define STAGE_BYTES (A_BYTES + B_BYTES)
#define SMEM_MAIN   (STAGES * STAGE_BYTES)   // 196608
#define NCHUNK      12

__global__ __launch_bounds__(256, 1)
void tal_main_kernel(const float* __restrict__ bias, float* __restrict__ out)
{
    extern __shared__ char smem[];
    const uint32_t sb = smem_u32(smem);

    const int bx   = blockIdx.x;          // 0..8
    const int g    = bx / 3, mt = bx % 3;  // mt: 256-row M tile
    const int col0 = blockIdx.y * 128;
    const int tid  = threadIdx.x;
    const int lane = tid & 31, warp = tid >> 5;
    const int wm = warp & 3, wn = warp >> 2;      // 4x2 warp grid, 64x64 tiles
    const int lr = lane >> 2, lc = lane & 3;

    // ---- cp.async addressing: one base each; constant strides ----
    const int r0 = tid >> 3, q8 = (tid & 7) * 8;        // 8 halfs = 16B granule
    const uint32_t dst0 = SWZ((uint32_t)(r0 * 128 + q8 * 2));
    const __half* aptr = g_wth + (size_t)(g * 768 + mt * 256 + r0) * 768 + q8;
    const __half* bptr = g_xsh[g] + (size_t)(col0 + r0) * 768 + q8;

    // ---- ldmatrix base offsets (ks=0); per-ks addr = base ^ (ks*32) ----
    const int alrow = lane & 15, aqhi = lane >> 4;
    const int brow = (lane & 7) | ((lane & 16) >> 1), bq = (lane >> 3) & 1;
    uint32_t aoff[4], boff[4];
    #pragma unroll
    for (int mi = 0; mi < 4; mi++)
        aoff[mi] = SWZ((uint32_t)((wm * 64 + mi * 16 + alrow) * 128 + aqhi * 16));
    #pragma unroll
    for (int nj = 0; nj < 4; nj++)
        boff[nj] = SWZ((uint32_t)((wn * 64 + nj * 16 + brow) * 128 + bq * 16));

    float acc[4][8][4];
    #pragma unroll
    for (int mi = 0; mi < 4; mi++)
        #pragma unroll
        for (int ni = 0; ni < 8; ni++)
            #pragma unroll
            for (int e = 0; e < 4; e++) acc[mi][ni][e] = 0.f;

    auto COPY = [&](int st, int c) {
        const uint32_t sA = sb + st * STAGE_BYTES;
        const uint32_t sB = sA + A_BYTES;
        const __half* ap = aptr + c * 64;
        const __half* bp = bptr + c * 64;
        #pragma unroll
        for (int i = 0; i < 8; i++)            // A: 256 rows, 32 rows/pass
            cp_async16(sA + dst0 + i * 4096, ap + i * 24576);
        #pragma unroll
        for (int i = 0; i < 4; i++)            // B: 128 rows, 32 rows/pass
            cp_async16(sB + dst0 + i * 4096, bp + i * 24576);
    };

    COPY(0, 0); CP_COMMIT();
    COPY(1, 1); CP_COMMIT();
    COPY(2, 2); CP_COMMIT();

    #pragma unroll 1
    for (int c = 0; c < NCHUNK; c++) {
        if (c <= NCHUNK - 3)      { CP_WAIT2(); }
        else if (c == NCHUNK - 2) { CP_WAIT1(); }
        else                      { CP_WAIT0(); }
        __syncthreads();
        if (c + 3 < NCHUNK) { COPY((c + 3) & 3, c + 3); CP_COMMIT(); }

        const uint32_t sA = sb + (c & 3) * STAGE_BYTES;
        const uint32_t sB = sA + A_BYTES;

        #pragma unroll
        for (int ks = 0; ks < 4; ks++) {           // k16 steps within 64-half chunk
            const uint32_t kx = (uint32_t)(ks * 32);
            uint32_t a[4][4], b[4][4];
            #pragma unroll
            for (int mi = 0; mi < 4; mi++)
                LDSM_X4(a[mi][0], a[mi][1], a[mi][2], a[mi][3], sA + (aoff[mi] ^ kx));
            #pragma unroll
            for (int nj = 0; nj < 4; nj++)
                LDSM_X4(b[nj][0], b[nj][1], b[nj][2], b[nj][3], sB + (boff[nj] ^ kx));
            #pragma unroll
            for (int mi = 0; mi < 4; mi++)
                #pragma unroll
                for (int ni = 0; ni < 8; ni++) {
                    const uint32_t b0 = b[ni >> 1][(ni & 1) * 2];
                    const uint32_t b1 = b[ni >> 1][(ni & 1) * 2 + 1];
                    asm volatile(
                        "mma.sync.aligned.m16n8k16.row.col.f32.f16.f16.f32 "
                        "{%0,%1,%2,%3},{%4,%5,%6,%7},{%8,%9},{%0,%1,%2,%3};\n"
                        : "+f"(acc[mi][ni][0]), "+f"(acc[mi][ni][1]),
                          "+f"(acc[mi][ni][2]), "+f"(acc[mi][ni][3])
                        : "r"(a[mi][0]), "r"(a[mi][1]), "r"(a[mi][2]), "r"(a[mi][3]),
                          "r"(b0), "r"(b1));
                }
        }
    }

    // ---- epilogue: out[bt, oc, n] = acc + bias[oc]*s[bt,oc] ----
    const int bt_base = col0 / 197;
    const int col197  = (bt_base + 1) * 197;
    int bt1 = bt_base + 1; if (bt1 > 127) bt1 = 127;

    float bvsv[4][2][2];
    #pragma unroll
    for (int mi = 0; mi < 4; mi++)
        #pragma unroll
        for (int h = 0; h < 2; h++) {
            int oc = g * 768 + mt * 256 + wm * 64 + mi * 16 + lr + h * 8;
            float bv = bias[oc];
            bvsv[mi][h][0] = bv * g_s[bt_base * 2304 + oc];
            bvsv[mi][h][1] = bv * g_s[bt1 * 2304 + oc];
        }

    #pragma unroll
    for (int mi = 0; mi < 4; mi++)
        #pragma unroll
        for (int ni = 0; ni < 8; ni++)
            #pragma unroll
            for (int e = 0; e < 4; e++) {
                const int h   = e >> 1;
                const int oc  = g * 768 + mt * 256 + wm * 64 + mi * 16 + lr + h * 8;
                const int col = col0 + wn * 64 + ni * 8 + lc * 2 + (e & 1);
                const int bs  = (col >= col197) ? 1 : 0;
                const float add = bs ? bvsv[mi][h][1] : bvsv[mi][h][0];
                // idx = bt*OUTBT + oc*197 + (col - bt*197) = col + oc*197 + bt*453691
                const size_t idx = (size_t)col + (size_t)oc * 197
                                 + (size_t)(bt_base + bs) * 453691;
                out[idx] = acc[mi][ni][e] + add;
            }
}

extern "C" void kernel_launch(void* const* d_in, const int* in_sizes, int n_in,
                              void* d_out, int out_size)
{
    const float* x    = (const float*)d_in[0];
    const float* aw   = (const float*)d_in[1];
    const float* ab   = (const float*)d_in[2];
    const float* w    = (const float*)d_in[3];
    const float* bias = (const float*)d_in[4];
    float* out = (float*)d_out;

    cudaFuncSetAttribute(tal_main_kernel,
                         cudaFuncAttributeMaxDynamicSharedMemorySize, SMEM_MAIN);

    routing_kernel<<<dim3(16, 9), 256>>>(x, aw, ab);
    prep_w<<<OC3 * 768 / 1024, 256>>>(w);
    prep_xs<<<NCOLS, 192>>>(x);
    tal_main_kernel<<<dim3(9, 197), 256, SMEM_MAIN>>>(bias, out);
}

// round 13
// speedup vs baseline: 1.9726x; 1.3166x over previous
#include <cuda_runtime.h>
#include <cuda_fp16.h>
#include <cstdint>

// ---------------- problem constants ----------------
#define NTOK  197
#define BTOT  128          // B*T
#define OC3   2304         // 3*C
#define NCOLS 25216        // BTOT*NTOK
#define OUTBT 453888       // OC3*NTOK

// ---------------- device scratch (static globals: allowed) ----------------
__device__ float  g_s[BTOT * OC3];              // routing scales, 1.18 MB
__device__ __half g_wth[OC3 * 768];             // fp16(W), 3.5 MB
__device__ __half g_xsh[3][NCOLS * 768];        // fp16(x*s) per group, 116 MB
__device__ __half g_awh[OC3 * 2304];            // fp16(a_weight), 10.6 MB
__device__ __half g_clsh[BTOT * 2304];          // fp16 im2col cls, 0.59 MB

// ---------------- helpers ----------------
__device__ __forceinline__ uint32_t smem_u32(const void* p) {
    uint32_t a;
    asm("{ .reg .u64 t; cvta.to.shared.u64 t, %1; cvt.u32.u64 %0, t; }" : "=r"(a) : "l"(p));
    return a;
}
__device__ __forceinline__ void cp_async16(uint32_t dst, const void* src) {
    asm volatile("cp.async.cg.shared.global [%0], [%1], 16;" :: "r"(dst), "l"(src) : "memory");
}
#define CP_COMMIT() asm volatile("cp.async.commit_group;" ::: "memory")
#define CP_WAIT1()  asm volatile("cp.async.wait_group 1;" ::: "memory")

#define LDSM_X4(r0, r1, r2, r3, addr) \
    asm volatile("ldmatrix.sync.aligned.m8n8.x4.shared.b16 {%0,%1,%2,%3}, [%4];" \
        : "=r"(r0), "=r"(r1), "=r"(r2), "=r"(r3) : "r"(addr))

#define SWZ(off) ((off) ^ (((off) >> 3) & 0x70))

#define MMA16816(acc, a, b0, b1) \
    asm volatile( \
        "mma.sync.aligned.m16n8k16.row.col.f32.f16.f16.f32 " \
        "{%0,%1,%2,%3},{%4,%5,%6,%7},{%8,%9},{%0,%1,%2,%3};\n" \
        : "+f"((acc)[0]), "+f"((acc)[1]), "+f"((acc)[2]), "+f"((acc)[3]) \
        : "r"((a)[0]), "r"((a)[1]), "r"((a)[2]), "r"((a)[3]), "r"(b0), "r"(b1))

// ---------------------------------------------------------------------------
// prep_awh: a_weight fp32 -> fp16 (layout already [oc][ic*3+k] contiguous)
// ---------------------------------------------------------------------------
__global__ __launch_bounds__(256) void prep_awh(const float* __restrict__ aw)
{
    int i = (blockIdx.x * 256 + threadIdx.x) * 4;
    float4 v = *(const float4*)(aw + i);
    __half2 h0 = __floats2half2_rn(v.x, v.y);
    __half2 h1 = __floats2half2_rn(v.z, v.w);
    uint2 o = { *(uint32_t*)&h0, *(uint32_t*)&h1 };
    *(uint2*)(&g_awh[i]) = o;
}

// ---------------------------------------------------------------------------
// build_cls: im2col of CLS tokens -> fp16
// g_clsh[bt][ic*3+k] = x[(b*8 + t+k-1)*197*768 + ic]  (zero outside t+k-1 in [0,8))
// grid = 128 (bt), block 256
// ---------------------------------------------------------------------------
__global__ __launch_bounds__(256) void build_cls(const float* __restrict__ x)
{
    const int bt = blockIdx.x;
    const int b  = bt >> 3, t = bt & 7;
    __half* dst = g_clsh + (size_t)bt * 2304;
    for (int j = threadIdx.x; j < 2304; j += 256) {
        const int ic = j / 3, k = j - ic * 3;
        const int tq = t + k - 1;
        float v = 0.f;
        if (tq >= 0 && tq < 8)
            v = x[(size_t)((b * 8 + tq) * 197) * 768 + ic];
        dst[j] = __float2half_rn(v);
    }
}

// ---------------------------------------------------------------------------
// routing_gemm: r[oc, bt] = sum_j awh[oc,j]*clsh[bt,j] ; g_s = r + ab + 1
// M=2304 (18 tiles of 128), N=128 (one tile), K=2304 (36 chunks of 64 halfs).
// Same machinery as main kernel. grid = 18, block 128.
// ---------------------------------------------------------------------------
#define RSTAGES      3
#define RSTAGE_BYTES 32768
#define SMEM_RT      (RSTAGES * RSTAGE_BYTES)
#define RNCHUNK      36

__global__ __launch_bounds__(128, 2)
void routing_gemm(const float* __restrict__ ab)
{
    extern __shared__ char smem[];
    const uint32_t sb = smem_u32(smem);

    const int mt   = blockIdx.x;          // 128-oc tile
    const int tid  = threadIdx.x;
    const int lane = tid & 31, warp = tid >> 5;
    const int wm = warp & 1, wn = warp >> 1;
    const int lr = lane >> 2, lc = lane & 3;

    const int r0 = tid >> 3, q8 = (tid & 7) * 8;
    const uint32_t dst0 = SWZ((uint32_t)(r0 * 128 + q8 * 2));
    const __half* aptr = g_awh + (size_t)(mt * 128 + r0) * 2304 + q8;
    const __half* bptr = g_clsh + (size_t)r0 * 2304 + q8;

    const int alrow = lane & 15, aqhi = lane >> 4;
    const int brow = (lane & 7) | ((lane & 16) >> 1), bq = (lane >> 3) & 1;
    uint32_t aoff[4], boff[4];
    #pragma unroll
    for (int mi = 0; mi < 4; mi++)
        aoff[mi] = SWZ((uint32_t)((wm * 64 + mi * 16 + alrow) * 128 + aqhi * 16));
    #pragma unroll
    for (int nj = 0; nj < 4; nj++)
        boff[nj] = SWZ((uint32_t)((wn * 64 + nj * 16 + brow) * 128 + bq * 16));

    float acc[4][8][4];
    #pragma unroll
    for (int mi = 0; mi < 4; mi++)
        #pragma unroll
        for (int ni = 0; ni < 8; ni++)
            #pragma unroll
            for (int e = 0; e < 4; e++) acc[mi][ni][e] = 0.f;

    auto COPY = [&](int st, int c) {
        const uint32_t sA = sb + st * RSTAGE_BYTES;
        const uint32_t sB = sA + 16384;
        const __half* ap = aptr + c * 64;
        const __half* bp = bptr + c * 64;
        #pragma unroll
        for (int i = 0; i < 8; i++) {
            cp_async16(sA + dst0 + i * 2048, ap + (size_t)i * 36864);
            cp_async16(sB + dst0 + i * 2048, bp + (size_t)i * 36864);
        }
    };

    COPY(0, 0); CP_COMMIT();
    COPY(1, 1); CP_COMMIT();

    int st = 0, pf = 2;
    #pragma unroll 1
    for (int c = 0; c < RNCHUNK; c++) {
        CP_WAIT1();
        __syncthreads();
        if (c + 2 < RNCHUNK) COPY(pf, c + 2);
        CP_COMMIT();

        const uint32_t sA = sb + st * RSTAGE_BYTES;
        const uint32_t sB = sA + 16384;
        #pragma unroll
        for (int ks = 0; ks < 4; ks++) {
            const uint32_t kx = (uint32_t)(ks * 32);
            uint32_t a[4][4], b[4][4];
            #pragma unroll
            for (int mi = 0; mi < 4; mi++)
                LDSM_X4(a[mi][0], a[mi][1], a[mi][2], a[mi][3], sA + (aoff[mi] ^ kx));
            #pragma unroll
            for (int nj = 0; nj < 4; nj++)
                LDSM_X4(b[nj][0], b[nj][1], b[nj][2], b[nj][3], sB + (boff[nj] ^ kx));
            #pragma unroll
            for (int mi = 0; mi < 4; mi++)
                #pragma unroll
                for (int ni = 0; ni < 8; ni++)
                    MMA16816(acc[mi][ni], a[mi],
                             b[ni >> 1][(ni & 1) * 2], b[ni >> 1][(ni & 1) * 2 + 1]);
        }
        st = (st + 1 == 3) ? 0 : st + 1;
        pf = (pf + 1 == 3) ? 0 : pf + 1;
    }

    // epilogue: g_s[bt*2304 + oc] = acc + ab[oc] + 1
    #pragma unroll
    for (int mi = 0; mi < 4; mi++)
        #pragma unroll
        for (int ni = 0; ni < 8; ni++)
            #pragma unroll
            for (int e = 0; e < 4; e++) {
                const int h  = e >> 1;
                const int oc = mt * 128 + wm * 64 + mi * 16 + lr + h * 8;
                const int bt = wn * 64 + ni * 8 + lc * 2 + (e & 1);
                g_s[bt * 2304 + oc] = acc[mi][ni][e] + ab[oc] + 1.0f;
            }
}

// ---------------------------------------------------------------------------
// Prep: W -> fp16(RN) ;  x,s -> fp16(x*s) per group
// ---------------------------------------------------------------------------
__global__ __launch_bounds__(256) void prep_w(const float* __restrict__ w)
{
    int i = (blockIdx.x * 256 + threadIdx.x) * 4;
    float4 v = *(const float4*)(w + i);
    __half2 h0 = __floats2half2_rn(v.x, v.y);
    __half2 h1 = __floats2half2_rn(v.z, v.w);
    uint2 o = { *(uint32_t*)&h0, *(uint32_t*)&h1 };
    *(uint2*)(&g_wth[i]) = o;
}

__global__ __launch_bounds__(192) void prep_xs(const float* __restrict__ x)
{
    const int col = blockIdx.x;
    const int k   = threadIdx.x * 4;
    const int bt  = col / 197;
    float4 xv = *(const float4*)(x + (size_t)col * 768 + k);
    #pragma unroll
    for (int g = 0; g < 3; g++) {
        float4 sv = *(const float4*)(g_s + bt * 2304 + g * 768 + k);
        __half2 h0 = __floats2half2_rn(xv.x * sv.x, xv.y * sv.y);
        __half2 h1 = __floats2half2_rn(xv.z * sv.z, xv.w * sv.w);
        uint2 o = { *(uint32_t*)&h0, *(uint32_t*)&h1 };
        *(uint2*)(&g_xsh[g][(size_t)col * 768 + k]) = o;
    }
}

// ---------------------------------------------------------------------------
// Main GEMM (mma.sync fp16 m16n8k16): per g, out[o,cj] = sum_k Wh[o,k]*Xh[cj,k]
// CTA tile 128x128, BK=64 halfs, 12 chunks, 3-stage cp.async.
// 4 warps = 2(m) x 2(n): warp tile 64x64. 2 CTAs/SM. grid=(18,197), block 128.
// ---------------------------------------------------------------------------
#define STAGES      3
#define STAGE_BYTES 32768            // A 16K + B 16K
#define SMEM_MAIN   (STAGES * STAGE_BYTES)
#define NCHUNK      12

__global__ __launch_bounds__(128, 2)
void tal_main_kernel(const float* __restrict__ bias, float* __restrict__ out)
{
    extern __shared__ char smem[];
    const uint32_t sb = smem_u32(smem);

    const int bx   = blockIdx.x;
    const int g    = bx / 6, mt = bx % 6;
    const int col0 = blockIdx.y * 128;
    const int tid  = threadIdx.x;
    const int lane = tid & 31, warp = tid >> 5;
    const int wm = warp & 1, wn = warp >> 1;      // 2x2 warp grid, 64x64 tiles
    const int lr = lane >> 2, lc = lane & 3;

    const int r0 = tid >> 3, q8 = (tid & 7) * 8;
    const uint32_t dst0 = SWZ((uint32_t)(r0 * 128 + q8 * 2));
    const __half* aptr = g_wth + (size_t)(g * 768 + mt * 128 + r0) * 768 + q8;
    const __half* bptr = g_xsh[g] + (size_t)(col0 + r0) * 768 + q8;

    const int alrow = lane & 15, aqhi = lane >> 4;
    const int brow = (lane & 7) | ((lane & 16) >> 1), bq = (lane >> 3) & 1;
    uint32_t aoff[4], boff[4];
    #pragma unroll
    for (int mi = 0; mi < 4; mi++)
        aoff[mi] = SWZ((uint32_t)((wm * 64 + mi * 16 + alrow) * 128 + aqhi * 16));
    #pragma unroll
    for (int nj = 0; nj < 4; nj++)
        boff[nj] = SWZ((uint32_t)((wn * 64 + nj * 16 + brow) * 128 + bq * 16));

    float acc[4][8][4];
    #pragma unroll
    for (int mi = 0; mi < 4; mi++)
        #pragma unroll
        for (int ni = 0; ni < 8; ni++)
            #pragma unroll
            for (int e = 0; e < 4; e++) acc[mi][ni][e] = 0.f;

    auto COPY = [&](int st, int c) {
        const uint32_t sA = sb + st * STAGE_BYTES;
        const uint32_t sB = sA + 16384;
        const __half* ap = aptr + c * 64;
        const __half* bp = bptr + c * 64;
        #pragma unroll
        for (int i = 0; i < 8; i++) {
            cp_async16(sA + dst0 + i * 2048, ap + i * 12288);
            cp_async16(sB + dst0 + i * 2048, bp + i * 12288);
        }
    };

    COPY(0, 0); CP_COMMIT();
    COPY(1, 1); CP_COMMIT();

    int st = 0, pf = 2;
    #pragma unroll 1
    for (int c = 0; c < NCHUNK; c++) {
        CP_WAIT1();
        __syncthreads();
        if (c + 2 < NCHUNK) COPY(pf, c + 2);
        CP_COMMIT();

        const uint32_t sA = sb + st * STAGE_BYTES;
        const uint32_t sB = sA + 16384;

        #pragma unroll
        for (int ks = 0; ks < 4; ks++) {
            const uint32_t kx = (uint32_t)(ks * 32);
            uint32_t a[4][4], b[4][4];
            #pragma unroll
            for (int mi = 0; mi < 4; mi++)
                LDSM_X4(a[mi][0], a[mi][1], a[mi][2], a[mi][3], sA + (aoff[mi] ^ kx));
            #pragma unroll
            for (int nj = 0; nj < 4; nj++)
                LDSM_X4(b[nj][0], b[nj][1], b[nj][2], b[nj][3], sB + (boff[nj] ^ kx));
            #pragma unroll
            for (int mi = 0; mi < 4; mi++)
                #pragma unroll
                for (int ni = 0; ni < 8; ni++)
                    MMA16816(acc[mi][ni], a[mi],
                             b[ni >> 1][(ni & 1) * 2], b[ni >> 1][(ni & 1) * 2 + 1]);
        }
        st = (st + 1 == 3) ? 0 : st + 1;
        pf = (pf + 1 == 3) ? 0 : pf + 1;
    }

    // ---- epilogue: out[bt, oc, n] = acc + bias[oc]*s[bt,oc] ----
    const int bt_base = col0 / 197;
    const int col197  = (bt_base + 1) * 197;
    int bt1 = bt_base + 1; if (bt1 > 127) bt1 = 127;

    float bvsv[4][2][2];
    #pragma unroll
    for (int mi = 0; mi < 4; mi++)
        #pragma unroll
        for (int h = 0; h < 2; h++) {
            int oc = g * 768 + mt * 128 + wm * 64 + mi * 16 + lr + h * 8;
            float bv = bias[oc];
            bvsv[mi][h][0] = bv * g_s[bt_base * 2304 + oc];
            bvsv[mi][h][1] = bv * g_s[bt1 * 2304 + oc];
        }

    #pragma unroll
    for (int mi = 0; mi < 4; mi++)
        #pragma unroll
        for (int ni = 0; ni < 8; ni++)
            #pragma unroll
            for (int e = 0; e < 4; e++) {
                const int h   = e >> 1;
                const int oc  = g * 768 + mt * 128 + wm * 64 + mi * 16 + lr + h * 8;
                const int col = col0 + wn * 64 + ni * 8 + lc * 2 + (e & 1);
                const int bs  = (col >= col197) ? 1 : 0;
                const float add = bs ? bvsv[mi][h][1] : bvsv[mi][h][0];
                const size_t idx = (size_t)col + (size_t)oc * 197
                                 + (size_t)(bt_base + bs) * 453691;
                out[idx] = acc[mi][ni][e] + add;
            }
}

extern "C" void kernel_launch(void* const* d_in, const int* in_sizes, int n_in,
                              void* d_out, int out_size)
{
    const float* x    = (const float*)d_in[0];
    const float* aw   = (const float*)d_in[1];
    const float* ab   = (const float*)d_in[2];
    const float* w    = (const float*)d_in[3];
    const float* bias = (const float*)d_in[4];
    float* out = (float*)d_out;

    cudaFuncSetAttribute(tal_main_kernel,
                         cudaFuncAttributeMaxDynamicSharedMemorySize, SMEM_MAIN);
    cudaFuncSetAttribute(routing_gemm,
                         cudaFuncAttributeMaxDynamicSharedMemorySize, SMEM_RT);

    prep_awh<<<OC3 * 2304 / 1024, 256>>>(aw);
    build_cls<<<BTOT, 256>>>(x);
    prep_w<<<OC3 * 768 / 1024, 256>>>(w);
    routing_gemm<<<18, 128, SMEM_RT>>>(ab);
    prep_xs<<<NCOLS, 192>>>(x);
    tal_main_kernel<<<dim3(18, 197), 128, SMEM_MAIN>>>(bias, out);
}

// round 14
// speedup vs baseline: 2.1184x; 1.0739x over previous
#include <cuda_runtime.h>
#include <cuda_fp16.h>
#include <cstdint>

// ---------------- problem constants ----------------
#define NTOK  197
#define BTOT  128          // B*T
#define OC3   2304         // 3*C
#define NCOLS 25216        // BTOT*NTOK
#define OUTBT 453888       // OC3*NTOK

// ---------------- device scratch (static globals: allowed) ----------------
__device__ float  g_s[BTOT * OC3];              // routing scales, 1.18 MB
__device__ float  g_rp[4][BTOT * OC3];          // split-K partials, 4.7 MB
__device__ __half g_wth[OC3 * 768];             // fp16(W), 3.5 MB
__device__ __half g_xsh[3][NCOLS * 768];        // fp16(x*s) per group, 116 MB
__device__ __half g_awh[OC3 * 2304];            // fp16(a_weight), 10.6 MB
__device__ __half g_clsh[BTOT * 2304];          // fp16 im2col cls, 0.59 MB

// ---------------- helpers ----------------
__device__ __forceinline__ uint32_t smem_u32(const void* p) {
    uint32_t a;
    asm("{ .reg .u64 t; cvta.to.shared.u64 t, %1; cvt.u32.u64 %0, t; }" : "=r"(a) : "l"(p));
    return a;
}
__device__ __forceinline__ void cp_async16(uint32_t dst, const void* src) {
    asm volatile("cp.async.cg.shared.global [%0], [%1], 16;" :: "r"(dst), "l"(src) : "memory");
}
#define CP_COMMIT() asm volatile("cp.async.commit_group;" ::: "memory")
#define CP_WAIT1()  asm volatile("cp.async.wait_group 1;" ::: "memory")

#define LDSM_X4(r0, r1, r2, r3, addr) \
    asm volatile("ldmatrix.sync.aligned.m8n8.x4.shared.b16 {%0,%1,%2,%3}, [%4];" \
        : "=r"(r0), "=r"(r1), "=r"(r2), "=r"(r3) : "r"(addr))

#define SWZ(off) ((off) ^ (((off) >> 3) & 0x70))

#define MMA16816(acc, a, b0, b1) \
    asm volatile( \
        "mma.sync.aligned.m16n8k16.row.col.f32.f16.f16.f32 " \
        "{%0,%1,%2,%3},{%4,%5,%6,%7},{%8,%9},{%0,%1,%2,%3};\n" \
        : "+f"((acc)[0]), "+f"((acc)[1]), "+f"((acc)[2]), "+f"((acc)[3]) \
        : "r"((a)[0]), "r"((a)[1]), "r"((a)[2]), "r"((a)[3]), "r"(b0), "r"(b1))

// ---------------------------------------------------------------------------
// prep_awh: a_weight fp32 -> fp16 (layout already [oc][ic*3+k] contiguous)
// ---------------------------------------------------------------------------
__global__ __launch_bounds__(256) void prep_awh(const float* __restrict__ aw)
{
    int i = (blockIdx.x * 256 + threadIdx.x) * 4;
    float4 v = *(const float4*)(aw + i);
    __half2 h0 = __floats2half2_rn(v.x, v.y);
    __half2 h1 = __floats2half2_rn(v.z, v.w);
    uint2 o = { *(uint32_t*)&h0, *(uint32_t*)&h1 };
    *(uint2*)(&g_awh[i]) = o;
}

// ---------------------------------------------------------------------------
// build_cls: im2col of CLS tokens -> fp16
// g_clsh[bt][ic*3+k] = x[(b*8 + t+k-1)*197*768 + ic]  (zero outside [0,8))
// ---------------------------------------------------------------------------
__global__ __launch_bounds__(256) void build_cls(const float* __restrict__ x)
{
    const int bt = blockIdx.x;
    const int b  = bt >> 3, t = bt & 7;
    __half* dst = g_clsh + (size_t)bt * 2304;
    for (int j = threadIdx.x; j < 2304; j += 256) {
        const int ic = j / 3, k = j - ic * 3;
        const int tq = t + k - 1;
        float v = 0.f;
        if (tq >= 0 && tq < 8)
            v = x[(size_t)((b * 8 + tq) * 197) * 768 + ic];
        dst[j] = __float2half_rn(v);
    }
}

// ---------------------------------------------------------------------------
// routing_gemm (split-K x4): partial[oc, bt] = sum_{j in K-slice} awh*clsh
// grid = (18 m-tiles, 4 k-slices), block 128. 9 chunks each.
// ---------------------------------------------------------------------------
#define RSTAGES      3
#define RSTAGE_BYTES 32768
#define SMEM_RT      (RSTAGES * RSTAGE_BYTES)
#define RNCHUNK      9           // 2304/4/64

__global__ __launch_bounds__(128, 2)
void routing_gemm()
{
    extern __shared__ char smem[];
    const uint32_t sb = smem_u32(smem);

    const int mt   = blockIdx.x;          // 128-oc tile
    const int ky   = blockIdx.y;          // K slice
    const int tid  = threadIdx.x;
    const int lane = tid & 31, warp = tid >> 5;
    const int wm = warp & 1, wn = warp >> 1;
    const int lr = lane >> 2, lc = lane & 3;

    const int r0 = tid >> 3, q8 = (tid & 7) * 8;
    const uint32_t dst0 = SWZ((uint32_t)(r0 * 128 + q8 * 2));
    const __half* aptr = g_awh + (size_t)(mt * 128 + r0) * 2304 + ky * 576 + q8;
    const __half* bptr = g_clsh + (size_t)r0 * 2304 + ky * 576 + q8;

    const int alrow = lane & 15, aqhi = lane >> 4;
    const int brow = (lane & 7) | ((lane & 16) >> 1), bq = (lane >> 3) & 1;
    uint32_t aoff[4], boff[4];
    #pragma unroll
    for (int mi = 0; mi < 4; mi++)
        aoff[mi] = SWZ((uint32_t)((wm * 64 + mi * 16 + alrow) * 128 + aqhi * 16));
    #pragma unroll
    for (int nj = 0; nj < 4; nj++)
        boff[nj] = SWZ((uint32_t)((wn * 64 + nj * 16 + brow) * 128 + bq * 16));

    float acc[4][8][4];
    #pragma unroll
    for (int mi = 0; mi < 4; mi++)
        #pragma unroll
        for (int ni = 0; ni < 8; ni++)
            #pragma unroll
            for (int e = 0; e < 4; e++) acc[mi][ni][e] = 0.f;

    auto COPY = [&](int st, int c) {
        const uint32_t sA = sb + st * RSTAGE_BYTES;
        const uint32_t sB = sA + 16384;
        const __half* ap = aptr + c * 64;
        const __half* bp = bptr + c * 64;
        #pragma unroll
        for (int i = 0; i < 8; i++) {
            cp_async16(sA + dst0 + i * 2048, ap + (size_t)i * 36864);
            cp_async16(sB + dst0 + i * 2048, bp + (size_t)i * 36864);
        }
    };

    COPY(0, 0); CP_COMMIT();
    COPY(1, 1); CP_COMMIT();

    int st = 0, pf = 2;
    #pragma unroll 1
    for (int c = 0; c < RNCHUNK; c++) {
        CP_WAIT1();
        __syncthreads();
        if (c + 2 < RNCHUNK) COPY(pf, c + 2);
        CP_COMMIT();

        const uint32_t sA = sb + st * RSTAGE_BYTES;
        const uint32_t sB = sA + 16384;
        #pragma unroll
        for (int ks = 0; ks < 4; ks++) {
            const uint32_t kx = (uint32_t)(ks * 32);
            uint32_t a[4][4], b[4][4];
            #pragma unroll
            for (int mi = 0; mi < 4; mi++)
                LDSM_X4(a[mi][0], a[mi][1], a[mi][2], a[mi][3], sA + (aoff[mi] ^ kx));
            #pragma unroll
            for (int nj = 0; nj < 4; nj++)
                LDSM_X4(b[nj][0], b[nj][1], b[nj][2], b[nj][3], sB + (boff[nj] ^ kx));
            #pragma unroll
            for (int mi = 0; mi < 4; mi++)
                #pragma unroll
                for (int ni = 0; ni < 8; ni++)
                    MMA16816(acc[mi][ni], a[mi],
                             b[ni >> 1][(ni & 1) * 2], b[ni >> 1][(ni & 1) * 2 + 1]);
        }
        st = (st + 1 == 3) ? 0 : st + 1;
        pf = (pf + 1 == 3) ? 0 : pf + 1;
    }

    // epilogue: deterministic partial store
    float* rp = g_rp[ky];
    #pragma unroll
    for (int mi = 0; mi < 4; mi++)
        #pragma unroll
        for (int ni = 0; ni < 8; ni++)
            #pragma unroll
            for (int e = 0; e < 4; e++) {
                const int h  = e >> 1;
                const int oc = mt * 128 + wm * 64 + mi * 16 + lr + h * 8;
                const int bt = wn * 64 + ni * 8 + lc * 2 + (e & 1);
                rp[bt * 2304 + oc] = acc[mi][ni][e];
            }
}

// ---------------------------------------------------------------------------
// combine_s: g_s = ab + 1 + sum of 4 partials (deterministic)
// ---------------------------------------------------------------------------
__global__ __launch_bounds__(256) void combine_s(const float* __restrict__ ab)
{
    int i4 = (blockIdx.x * 256 + threadIdx.x) * 4;   // < 294912
    int oc = i4 % 2304;
    float4 a  = *(const float4*)(ab + oc);
    float4 r0 = *(const float4*)(&g_rp[0][i4]);
    float4 r1 = *(const float4*)(&g_rp[1][i4]);
    float4 r2 = *(const float4*)(&g_rp[2][i4]);
    float4 r3 = *(const float4*)(&g_rp[3][i4]);
    float4 o;
    o.x = a.x + 1.0f + ((r0.x + r1.x) + (r2.x + r3.x));
    o.y = a.y + 1.0f + ((r0.y + r1.y) + (r2.y + r3.y));
    o.z = a.z + 1.0f + ((r0.z + r1.z) + (r2.z + r3.z));
    o.w = a.w + 1.0f + ((r0.w + r1.w) + (r2.w + r3.w));
    *(float4*)(&g_s[i4]) = o;
}

// ---------------------------------------------------------------------------
// Prep: W -> fp16(RN) ;  x,s -> fp16(x*s) per group (8 k per thread, 16B stores)
// ---------------------------------------------------------------------------
__global__ __launch_bounds__(256) void prep_w(const float* __restrict__ w)
{
    int i = (blockIdx.x * 256 + threadIdx.x) * 4;
    float4 v = *(const float4*)(w + i);
    __half2 h0 = __floats2half2_rn(v.x, v.y);
    __half2 h1 = __floats2half2_rn(v.z, v.w);
    uint2 o = { *(uint32_t*)&h0, *(uint32_t*)&h1 };
    *(uint2*)(&g_wth[i]) = o;
}

__global__ __launch_bounds__(256) void prep_xs(const float* __restrict__ x)
{
    const int gi  = blockIdx.x * 256 + threadIdx.x;   // < NCOLS*96
    const int col = gi / 96;
    const int k8  = (gi - col * 96) * 8;
    const int bt  = col / 197;
    const float* xp = x + (size_t)col * 768 + k8;
    float4 x0 = *(const float4*)xp;
    float4 x1 = *(const float4*)(xp + 4);
    #pragma unroll
    for (int g = 0; g < 3; g++) {
        const float* sp = g_s + bt * 2304 + g * 768 + k8;
        float4 s0 = *(const float4*)sp;
        float4 s1 = *(const float4*)(sp + 4);
        __half2 h0 = __floats2half2_rn(x0.x * s0.x, x0.y * s0.y);
        __half2 h1 = __floats2half2_rn(x0.z * s0.z, x0.w * s0.w);
        __half2 h2 = __floats2half2_rn(x1.x * s1.x, x1.y * s1.y);
        __half2 h3 = __floats2half2_rn(x1.z * s1.z, x1.w * s1.w);
        uint4 o = { *(uint32_t*)&h0, *(uint32_t*)&h1,
                    *(uint32_t*)&h2, *(uint32_t*)&h3 };
        *(uint4*)(&g_xsh[g][(size_t)col * 768 + k8]) = o;
    }
}

// ---------------------------------------------------------------------------
// Main GEMM (mma.sync fp16 m16n8k16): per g, out[o,cj] = sum_k Wh[o,k]*Xh[cj,k]
// CTA tile 128x128, BK=64 halfs, 12 chunks, 3-stage cp.async.
// 4 warps = 2(m) x 2(n): warp tile 64x64. 2 CTAs/SM. grid=(18,197), block 128.
// ---------------------------------------------------------------------------
#define STAGES      3
#define STAGE_BYTES 32768            // A 16K + B 16K
#define SMEM_MAIN   (STAGES * STAGE_BYTES)
#define NCHUNK      12

__global__ __launch_bounds__(128, 2)
void tal_main_kernel(const float* __restrict__ bias, float* __restrict__ out)
{
    extern __shared__ char smem[];
    const uint32_t sb = smem_u32(smem);

    const int bx   = blockIdx.x;
    const int g    = bx / 6, mt = bx % 6;
    const int col0 = blockIdx.y * 128;
    const int tid  = threadIdx.x;
    const int lane = tid & 31, warp = tid >> 5;
    const int wm = warp & 1, wn = warp >> 1;      // 2x2 warp grid, 64x64 tiles
    const int lr = lane >> 2, lc = lane & 3;

    const int r0 = tid >> 3, q8 = (tid & 7) * 8;
    const uint32_t dst0 = SWZ((uint32_t)(r0 * 128 + q8 * 2));
    const __half* aptr = g_wth + (size_t)(g * 768 + mt * 128 + r0) * 768 + q8;
    const __half* bptr = g_xsh[g] + (size_t)(col0 + r0) * 768 + q8;

    const int alrow = lane & 15, aqhi = lane >> 4;
    const int brow = (lane & 7) | ((lane & 16) >> 1), bq = (lane >> 3) & 1;
    uint32_t aoff[4], boff[4];
    #pragma unroll
    for (int mi = 0; mi < 4; mi++)
        aoff[mi] = SWZ((uint32_t)((wm * 64 + mi * 16 + alrow) * 128 + aqhi * 16));
    #pragma unroll
    for (int nj = 0; nj < 4; nj++)
        boff[nj] = SWZ((uint32_t)((wn * 64 + nj * 16 + brow) * 128 + bq * 16));

    float acc[4][8][4];
    #pragma unroll
    for (int mi = 0; mi < 4; mi++)
        #pragma unroll
        for (int ni = 0; ni < 8; ni++)
            #pragma unroll
            for (int e = 0; e < 4; e++) acc[mi][ni][e] = 0.f;

    auto COPY = [&](int st, int c) {
        const uint32_t sA = sb + st * STAGE_BYTES;
        const uint32_t sB = sA + 16384;
        const __half* ap = aptr + c * 64;
        const __half* bp = bptr + c * 64;
        #pragma unroll
        for (int i = 0; i < 8; i++) {
            cp_async16(sA + dst0 + i * 2048, ap + i * 12288);
            cp_async16(sB + dst0 + i * 2048, bp + i * 12288);
        }
    };

    COPY(0, 0); CP_COMMIT();
    COPY(1, 1); CP_COMMIT();

    int st = 0, pf = 2;
    #pragma unroll 1
    for (int c = 0; c < NCHUNK; c++) {
        CP_WAIT1();
        __syncthreads();
        if (c + 2 < NCHUNK) COPY(pf, c + 2);
        CP_COMMIT();

        const uint32_t sA = sb + st * STAGE_BYTES;
        const uint32_t sB = sA + 16384;

        #pragma unroll
        for (int ks = 0; ks < 4; ks++) {
            const uint32_t kx = (uint32_t)(ks * 32);
            uint32_t a[4][4], b[4][4];
            #pragma unroll
            for (int mi = 0; mi < 4; mi++)
                LDSM_X4(a[mi][0], a[mi][1], a[mi][2], a[mi][3], sA + (aoff[mi] ^ kx));
            #pragma unroll
            for (int nj = 0; nj < 4; nj++)
                LDSM_X4(b[nj][0], b[nj][1], b[nj][2], b[nj][3], sB + (boff[nj] ^ kx));
            #pragma unroll
            for (int mi = 0; mi < 4; mi++)
                #pragma unroll
                for (int ni = 0; ni < 8; ni++)
                    MMA16816(acc[mi][ni], a[mi],
                             b[ni >> 1][(ni & 1) * 2], b[ni >> 1][(ni & 1) * 2 + 1]);
        }
        st = (st + 1 == 3) ? 0 : st + 1;
        pf = (pf + 1 == 3) ? 0 : pf + 1;
    }

    // ---- epilogue: out[bt, oc, n] = acc + bias[oc]*s[bt,oc] ----
    const int bt_base = col0 / 197;
    const int col197  = (bt_base + 1) * 197;
    int bt1 = bt_base + 1; if (bt1 > 127) bt1 = 127;

    float bvsv[4][2][2];
    #pragma unroll
    for (int mi = 0; mi < 4; mi++)
        #pragma unroll
        for (int h = 0; h < 2; h++) {
            int oc = g * 768 + mt * 128 + wm * 64 + mi * 16 + lr + h * 8;
            float bv = bias[oc];
            bvsv[mi][h][0] = bv * g_s[bt_base * 2304 + oc];
            bvsv[mi][h][1] = bv * g_s[bt1 * 2304 + oc];
        }

    #pragma unroll
    for (int mi = 0; mi < 4; mi++)
        #pragma unroll
        for (int ni = 0; ni < 8; ni++)
            #pragma unroll
            for (int e = 0; e < 4; e++) {
                const int h   = e >> 1;
                const int oc  = g * 768 + mt * 128 + wm * 64 + mi * 16 + lr + h * 8;
                const int col = col0 + wn * 64 + ni * 8 + lc * 2 + (e & 1);
                const int bs  = (col >= col197) ? 1 : 0;
                const float add = bs ? bvsv[mi][h][1] : bvsv[mi][h][0];
                const size_t idx = (size_t)col + (size_t)oc * 197
                                 + (size_t)(bt_base + bs) * 453691;
                out[idx] = acc[mi][ni][e] + add;
            }
}

extern "C" void kernel_launch(void* const* d_in, const int* in_sizes, int n_in,
                              void* d_out, int out_size)
{
    const float* x    = (const float*)d_in[0];
    const float* aw   = (const float*)d_in[1];
    const float* ab   = (const float*)d_in[2];
    const float* w    = (const float*)d_in[3];
    const float* bias = (const float*)d_in[4];
    float* out = (float*)d_out;

    cudaFuncSetAttribute(tal_main_kernel,
                         cudaFuncAttributeMaxDynamicSharedMemorySize, SMEM_MAIN);
    cudaFuncSetAttribute(routing_gemm,
                         cudaFuncAttributeMaxDynamicSharedMemorySize, SMEM_RT);

    prep_awh<<<OC3 * 2304 / 1024, 256>>>(aw);
    build_cls<<<BTOT, 256>>>(x);
    prep_w<<<OC3 * 768 / 1024, 256>>>(w);
    routing_gemm<<<dim3(18, 4), 128, SMEM_RT>>>();
    combine_s<<<BTOT * OC3 / 1024, 256>>>(ab);
    prep_xs<<<NCOLS * 96 / 256, 256>>>(x);
    tal_main_kernel<<<dim3(18, 197), 128, SMEM_MAIN>>>(bias, out);
}

// round 15
// speedup vs baseline: 2.2037x; 1.0403x over previous
#include <cuda_runtime.h>
#include <cuda_fp16.h>
#include <cstdint>

// ---------------- problem constants ----------------
#define NTOK  197
#define BTOT  128          // B*T
#define OC3   2304         // 3*C
#define NCOLS 25216        // BTOT*NTOK
#define OUTBT 453888       // OC3*NTOK

// ---------------- device scratch (static globals: allowed) ----------------
__device__ float  g_s[BTOT * OC3];              // routing scales, 1.18 MB
__device__ float  g_rp[4][BTOT * OC3];          // split-K partials, 4.7 MB
__device__ __half g_wth[OC3 * 768];             // fp16(W), 3.5 MB
__device__ __half g_xsh[3][NCOLS * 768];        // fp16(x*s) per group, 116 MB
__device__ __half g_awh[OC3 * 2304];            // fp16(a_weight), 10.6 MB
__device__ __half g_clsh[BTOT * 2304];          // fp16 im2col cls, 0.59 MB

// ---------------- helpers ----------------
__device__ __forceinline__ uint32_t smem_u32(const void* p) {
    uint32_t a;
    asm("{ .reg .u64 t; cvta.to.shared.u64 t, %1; cvt.u32.u64 %0, t; }" : "=r"(a) : "l"(p));
    return a;
}
__device__ __forceinline__ void cp_async16(uint32_t dst, const void* src) {
    asm volatile("cp.async.cg.shared.global [%0], [%1], 16;" :: "r"(dst), "l"(src) : "memory");
}
#define CP_COMMIT() asm volatile("cp.async.commit_group;" ::: "memory")
#define CP_WAIT1()  asm volatile("cp.async.wait_group 1;" ::: "memory")

#define LDSM_X4(r0, r1, r2, r3, addr) \
    asm volatile("ldmatrix.sync.aligned.m8n8.x4.shared.b16 {%0,%1,%2,%3}, [%4];" \
        : "=r"(r0), "=r"(r1), "=r"(r2), "=r"(r3) : "r"(addr))

#define SWZ(off) ((off) ^ (((off) >> 3) & 0x70))

#define MMA16816(acc, a, b0, b1) \
    asm volatile( \
        "mma.sync.aligned.m16n8k16.row.col.f32.f16.f16.f32 " \
        "{%0,%1,%2,%3},{%4,%5,%6,%7},{%8,%9},{%0,%1,%2,%3};\n" \
        : "+f"((acc)[0]), "+f"((acc)[1]), "+f"((acc)[2]), "+f"((acc)[3]) \
        : "r"((a)[0]), "r"((a)[1]), "r"((a)[2]), "r"((a)[3]), "r"(b0), "r"(b1))

// ---------------------------------------------------------------------------
// prep_all: fused independent converters, dispatched by blockIdx range.
//   [0, 5184)        : a_weight fp32 -> fp16
//   [5184, 6912)     : W fp32 -> fp16
//   [6912, 7040)     : build_cls im2col fp16
// ---------------------------------------------------------------------------
__global__ __launch_bounds__(256) void prep_all(
    const float* __restrict__ aw, const float* __restrict__ w,
    const float* __restrict__ x)
{
    const int bid = blockIdx.x;
    if (bid < 5184) {
        int i = (bid * 256 + threadIdx.x) * 4;
        float4 v = *(const float4*)(aw + i);
        __half2 h0 = __floats2half2_rn(v.x, v.y);
        __half2 h1 = __floats2half2_rn(v.z, v.w);
        uint2 o = { *(uint32_t*)&h0, *(uint32_t*)&h1 };
        *(uint2*)(&g_awh[i]) = o;
    } else if (bid < 6912) {
        int i = ((bid - 5184) * 256 + threadIdx.x) * 4;
        float4 v = *(const float4*)(w + i);
        __half2 h0 = __floats2half2_rn(v.x, v.y);
        __half2 h1 = __floats2half2_rn(v.z, v.w);
        uint2 o = { *(uint32_t*)&h0, *(uint32_t*)&h1 };
        *(uint2*)(&g_wth[i]) = o;
    } else {
        const int bt = bid - 6912;
        const int b  = bt >> 3, t = bt & 7;
        __half* dst = g_clsh + (size_t)bt * 2304;
        for (int j = threadIdx.x; j < 2304; j += 256) {
            const int ic = j / 3, k = j - ic * 3;
            const int tq = t + k - 1;
            float v = 0.f;
            if (tq >= 0 && tq < 8)
                v = x[(size_t)((b * 8 + tq) * 197) * 768 + ic];
            dst[j] = __float2half_rn(v);
        }
    }
}

// ---------------------------------------------------------------------------
// routing_gemm (split-K x4): partial[oc, bt] = sum_{j in K-slice} awh*clsh
// grid = (18 m-tiles, 4 k-slices), block 128. 9 chunks each.
// ---------------------------------------------------------------------------
#define RSTAGES      3
#define RSTAGE_BYTES 32768
#define SMEM_RT      (RSTAGES * RSTAGE_BYTES)
#define RNCHUNK      9           // 2304/4/64

__global__ __launch_bounds__(128, 2)
void routing_gemm()
{
    extern __shared__ char smem[];
    const uint32_t sb = smem_u32(smem);

    const int mt   = blockIdx.x;          // 128-oc tile
    const int ky   = blockIdx.y;          // K slice
    const int tid  = threadIdx.x;
    const int lane = tid & 31, warp = tid >> 5;
    const int wm = warp & 1, wn = warp >> 1;
    const int lr = lane >> 2, lc = lane & 3;

    const int r0 = tid >> 3, q8 = (tid & 7) * 8;
    const uint32_t dst0 = SWZ((uint32_t)(r0 * 128 + q8 * 2));
    const __half* aptr = g_awh + (size_t)(mt * 128 + r0) * 2304 + ky * 576 + q8;
    const __half* bptr = g_clsh + (size_t)r0 * 2304 + ky * 576 + q8;

    const int alrow = lane & 15, aqhi = lane >> 4;
    const int brow = (lane & 7) | ((lane & 16) >> 1), bq = (lane >> 3) & 1;
    uint32_t aoff[4], boff[4];
    #pragma unroll
    for (int mi = 0; mi < 4; mi++)
        aoff[mi] = SWZ((uint32_t)((wm * 64 + mi * 16 + alrow) * 128 + aqhi * 16));
    #pragma unroll
    for (int nj = 0; nj < 4; nj++)
        boff[nj] = SWZ((uint32_t)((wn * 64 + nj * 16 + brow) * 128 + bq * 16));

    float acc[4][8][4];
    #pragma unroll
    for (int mi = 0; mi < 4; mi++)
        #pragma unroll
        for (int ni = 0; ni < 8; ni++)
            #pragma unroll
            for (int e = 0; e < 4; e++) acc[mi][ni][e] = 0.f;

    auto COPY = [&](int st, int c) {
        const uint32_t sA = sb + st * RSTAGE_BYTES;
        const uint32_t sB = sA + 16384;
        const __half* ap = aptr + c * 64;
        const __half* bp = bptr + c * 64;
        #pragma unroll
        for (int i = 0; i < 8; i++) {
            cp_async16(sA + dst0 + i * 2048, ap + (size_t)i * 36864);
            cp_async16(sB + dst0 + i * 2048, bp + (size_t)i * 36864);
        }
    };

    COPY(0, 0); CP_COMMIT();
    COPY(1, 1); CP_COMMIT();

    int st = 0, pf = 2;
    #pragma unroll 1
    for (int c = 0; c < RNCHUNK; c++) {
        CP_WAIT1();
        __syncthreads();
        if (c + 2 < RNCHUNK) COPY(pf, c + 2);
        CP_COMMIT();

        const uint32_t sA = sb + st * RSTAGE_BYTES;
        const uint32_t sB = sA + 16384;
        #pragma unroll
        for (int ks = 0; ks < 4; ks++) {
            const uint32_t kx = (uint32_t)(ks * 32);
            uint32_t a[4][4], b[4][4];
            #pragma unroll
            for (int mi = 0; mi < 4; mi++)
                LDSM_X4(a[mi][0], a[mi][1], a[mi][2], a[mi][3], sA + (aoff[mi] ^ kx));
            #pragma unroll
            for (int nj = 0; nj < 4; nj++)
                LDSM_X4(b[nj][0], b[nj][1], b[nj][2], b[nj][3], sB + (boff[nj] ^ kx));
            #pragma unroll
            for (int mi = 0; mi < 4; mi++)
                #pragma unroll
                for (int ni = 0; ni < 8; ni++)
                    MMA16816(acc[mi][ni], a[mi],
                             b[ni >> 1][(ni & 1) * 2], b[ni >> 1][(ni & 1) * 2 + 1]);
        }
        st = (st + 1 == 3) ? 0 : st + 1;
        pf = (pf + 1 == 3) ? 0 : pf + 1;
    }

    float* rp = g_rp[ky];
    #pragma unroll
    for (int mi = 0; mi < 4; mi++)
        #pragma unroll
        for (int ni = 0; ni < 8; ni++)
            #pragma unroll
            for (int e = 0; e < 4; e++) {
                const int h  = e >> 1;
                const int oc = mt * 128 + wm * 64 + mi * 16 + lr + h * 8;
                const int bt = wn * 64 + ni * 8 + lc * 2 + (e & 1);
                rp[bt * 2304 + oc] = acc[mi][ni][e];
            }
}

// ---------------------------------------------------------------------------
// combine_s: g_s = ab + 1 + sum of 4 partials (deterministic)
// ---------------------------------------------------------------------------
__global__ __launch_bounds__(256) void combine_s(const float* __restrict__ ab)
{
    int i4 = (blockIdx.x * 256 + threadIdx.x) * 4;   // < 294912
    int oc = i4 % 2304;
    float4 a  = *(const float4*)(ab + oc);
    float4 r0 = *(const float4*)(&g_rp[0][i4]);
    float4 r1 = *(const float4*)(&g_rp[1][i4]);
    float4 r2 = *(const float4*)(&g_rp[2][i4]);
    float4 r3 = *(const float4*)(&g_rp[3][i4]);
    float4 o;
    o.x = a.x + 1.0f + ((r0.x + r1.x) + (r2.x + r3.x));
    o.y = a.y + 1.0f + ((r0.y + r1.y) + (r2.y + r3.y));
    o.z = a.z + 1.0f + ((r0.z + r1.z) + (r2.z + r3.z));
    o.w = a.w + 1.0f + ((r0.w + r1.w) + (r2.w + r3.w));
    *(float4*)(&g_s[i4]) = o;
}

// ---------------------------------------------------------------------------
// prep_xs: x,s -> fp16(x*s) per group (8 k per thread, 16B stores)
// ---------------------------------------------------------------------------
__global__ __launch_bounds__(256) void prep_xs(const float* __restrict__ x)
{
    const int gi  = blockIdx.x * 256 + threadIdx.x;   // < NCOLS*96
    const int col = gi / 96;
    const int k8  = (gi - col * 96) * 8;
    const int bt  = col / 197;
    const float* xp = x + (size_t)col * 768 + k8;
    float4 x0 = *(const float4*)xp;
    float4 x1 = *(const float4*)(xp + 4);
    #pragma unroll
    for (int g = 0; g < 3; g++) {
        const float* sp = g_s + bt * 2304 + g * 768 + k8;
        float4 s0 = *(const float4*)sp;
        float4 s1 = *(const float4*)(sp + 4);
        __half2 h0 = __floats2half2_rn(x0.x * s0.x, x0.y * s0.y);
        __half2 h1 = __floats2half2_rn(x0.z * s0.z, x0.w * s0.w);
        __half2 h2 = __floats2half2_rn(x1.x * s1.x, x1.y * s1.y);
        __half2 h3 = __floats2half2_rn(x1.z * s1.z, x1.w * s1.w);
        uint4 o = { *(uint32_t*)&h0, *(uint32_t*)&h1,
                    *(uint32_t*)&h2, *(uint32_t*)&h3 };
        *(uint4*)(&g_xsh[g][(size_t)col * 768 + k8]) = o;
    }
}

// ---------------------------------------------------------------------------
// Main GEMM (mma.sync fp16 m16n8k16), PERSISTENT: grid=296 (2 CTA/SM).
// Each CTA walks tiles p, p+296, ... of 3546. CTA tile 128x128, BK=64, 12
// chunks, 3-stage cp.async ring continuous ACROSS tiles (12%3==0): during
// chunks 10-11 the copy slots prefetch next tile's chunks 0-1, so epilogue
// overlaps the refill. 4 warps = 2x2, warp tile 64x64.
// ---------------------------------------------------------------------------
#define STAGES      3
#define STAGE_BYTES 32768            // A 16K + B 16K
#define SMEM_MAIN   (STAGES * STAGE_BYTES)
#define NCHUNK      12
#define NT_TILES    3546             // 18 * 197
#define NPERS       296

__global__ __launch_bounds__(128, 2)
void tal_main_kernel(const float* __restrict__ bias, float* __restrict__ out)
{
    extern __shared__ char smem[];
    const uint32_t sb = smem_u32(smem);

    const int tid  = threadIdx.x;
    const int lane = tid & 31, warp = tid >> 5;
    const int wm = warp & 1, wn = warp >> 1;      // 2x2 warp grid, 64x64 tiles
    const int lr = lane >> 2, lc = lane & 3;

    const int r0 = tid >> 3, q8 = (tid & 7) * 8;
    const uint32_t dst0 = SWZ((uint32_t)(r0 * 128 + q8 * 2));

    const int alrow = lane & 15, aqhi = lane >> 4;
    const int brow = (lane & 7) | ((lane & 16) >> 1), bq = (lane >> 3) & 1;
    uint32_t aoff[4], boff[4];
    #pragma unroll
    for (int mi = 0; mi < 4; mi++)
        aoff[mi] = SWZ((uint32_t)((wm * 64 + mi * 16 + alrow) * 128 + aqhi * 16));
    #pragma unroll
    for (int nj = 0; nj < 4; nj++)
        boff[nj] = SWZ((uint32_t)((wn * 64 + nj * 16 + brow) * 128 + bq * 16));

    auto mk_ptrs = [&](int t, const __half*& ap, const __half*& bp) {
        const int bx = t % 18;
        const int y  = t / 18;
        const int g  = bx / 6, mt = bx % 6;
        ap = g_wth + (size_t)(g * 768 + mt * 128 + r0) * 768 + q8;
        bp = g_xsh[g] + (size_t)(y * 128 + r0) * 768 + q8;
    };
    auto COPY = [&](int st, const __half* ap, const __half* bp, int c) {
        const uint32_t sA = sb + st * STAGE_BYTES;
        const uint32_t sB = sA + 16384;
        const __half* a8 = ap + c * 64;
        const __half* b8 = bp + c * 64;
        #pragma unroll
        for (int i = 0; i < 8; i++) {
            cp_async16(sA + dst0 + i * 2048, a8 + i * 12288);
            cp_async16(sB + dst0 + i * 2048, b8 + i * 12288);
        }
    };

    int t = blockIdx.x;
    const __half *ap, *bp;
    mk_ptrs(t, ap, bp);
    COPY(0, ap, bp, 0); CP_COMMIT();
    COPY(1, ap, bp, 1); CP_COMMIT();

    while (true) {
        const int  tn       = t + NPERS;
        const bool has_next = tn < NT_TILES;
        const __half *apN = ap, *bpN = bp;
        if (has_next) mk_ptrs(tn, apN, bpN);

        float acc[4][8][4];
        #pragma unroll
        for (int mi = 0; mi < 4; mi++)
            #pragma unroll
            for (int ni = 0; ni < 8; ni++)
                #pragma unroll
                for (int e = 0; e < 4; e++) acc[mi][ni][e] = 0.f;

        #pragma unroll 1
        for (int c = 0; c < NCHUNK; c++) {
            CP_WAIT1();
            __syncthreads();
            const int pst = (c + 2) % 3;
            if (c < NCHUNK - 2)      COPY(pst, ap, bp, c + 2);
            else if (has_next)       COPY(pst, apN, bpN, c + 2 - NCHUNK);
            CP_COMMIT();

            const uint32_t sA = sb + (c % 3) * STAGE_BYTES;
            const uint32_t sB = sA + 16384;
            #pragma unroll
            for (int ks = 0; ks < 4; ks++) {
                const uint32_t kx = (uint32_t)(ks * 32);
                uint32_t a[4][4], b[4][4];
                #pragma unroll
                for (int mi = 0; mi < 4; mi++)
                    LDSM_X4(a[mi][0], a[mi][1], a[mi][2], a[mi][3], sA + (aoff[mi] ^ kx));
                #pragma unroll
                for (int nj = 0; nj < 4; nj++)
                    LDSM_X4(b[nj][0], b[nj][1], b[nj][2], b[nj][3], sB + (boff[nj] ^ kx));
                #pragma unroll
                for (int mi = 0; mi < 4; mi++)
                    #pragma unroll
                    for (int ni = 0; ni < 8; ni++)
                        MMA16816(acc[mi][ni], a[mi],
                                 b[ni >> 1][(ni & 1) * 2], b[ni >> 1][(ni & 1) * 2 + 1]);
            }
        }

        // ---- epilogue for tile t (overlaps in-flight next-tile copies) ----
        {
            const int bx = t % 18, y = t / 18;
            const int g = bx / 6, mt = bx % 6;
            const int col0 = y * 128;
            const int bt_base = col0 / 197;
            const int col197  = (bt_base + 1) * 197;
            int bt1 = bt_base + 1; if (bt1 > 127) bt1 = 127;

            float bvsv[4][2][2];
            #pragma unroll
            for (int mi = 0; mi < 4; mi++)
                #pragma unroll
                for (int h = 0; h < 2; h++) {
                    int oc = g * 768 + mt * 128 + wm * 64 + mi * 16 + lr + h * 8;
                    float bv = bias[oc];
                    bvsv[mi][h][0] = bv * g_s[bt_base * 2304 + oc];
                    bvsv[mi][h][1] = bv * g_s[bt1 * 2304 + oc];
                }

            #pragma unroll
            for (int mi = 0; mi < 4; mi++)
                #pragma unroll
                for (int ni = 0; ni < 8; ni++)
                    #pragma unroll
                    for (int e = 0; e < 4; e++) {
                        const int h   = e >> 1;
                        const int oc  = g * 768 + mt * 128 + wm * 64 + mi * 16 + lr + h * 8;
                        const int col = col0 + wn * 64 + ni * 8 + lc * 2 + (e & 1);
                        const int bs  = (col >= col197) ? 1 : 0;
                        const float add = bs ? bvsv[mi][h][1] : bvsv[mi][h][0];
                        const size_t idx = (size_t)col + (size_t)oc * 197
                                         + (size_t)(bt_base + bs) * 453691;
                        out[idx] = acc[mi][ni][e] + add;
                    }
        }

        if (!has_next) break;
        t = tn; ap = apN; bp = bpN;
    }
}

extern "C" void kernel_launch(void* const* d_in, const int* in_sizes, int n_in,
                              void* d_out, int out_size)
{
    const float* x    = (const float*)d_in[0];
    const float* aw   = (const float*)d_in[1];
    const float* ab   = (const float*)d_in[2];
    const float* w    = (const float*)d_in[3];
    const float* bias = (const float*)d_in[4];
    float* out = (float*)d_out;

    cudaFuncSetAttribute(tal_main_kernel,
                         cudaFuncAttributeMaxDynamicSharedMemorySize, SMEM_MAIN);
    cudaFuncSetAttribute(routing_gemm,
                         cudaFuncAttributeMaxDynamicSharedMemorySize, SMEM_RT);

    prep_all<<<7040, 256>>>(aw, w, x);
    routing_gemm<<<dim3(18, 4), 128, SMEM_RT>>>();
    combine_s<<<BTOT * OC3 / 1024, 256>>>(ab);
    prep_xs<<<NCOLS * 96 / 256, 256>>>(x);
    tal_main_kernel<<<NPERS, 128, SMEM_MAIN>>>(bias, out);
}